// round 10
// baseline (speedup 1.0000x reference)
#include <cuda_runtime.h>
#include <cuda_fp16.h>
#include <math.h>
#include <stdint.h>

#define NB 8
#define NT 1024
#define NC 1024
#define NH 16
#define NM (NB*NT)
#define KH 512            // K/2 (fp16 pairs packed along K)
#define NSEG 8
#define TSEG (NT/NSEG)

// ---------------- scratch (static device globals, no allocation) -------------
__device__ float    g_kvr [3*NM*NC];      // k, v, r
__device__ float    g_sumk[NM*NC];        // per-segment local cumsum
__device__ float    g_segtot[NB*NSEG*NC];
__device__ float    g_segoff[NB*NSEG*NC];
__device__ float    g_wkv [NM*NC];
__device__ uint32_t g_Ah  [NM*KH];        // packed f16x2 hi of current A operand
__device__ uint32_t g_Al  [NM*KH];        // packed f16x2 lo
__device__ uint32_t g_Wh  [4*NC*KH];      // Wk,Wv,Wr,Wo rounded to fp16 (B operand)
__device__ uint32_t g_WWh [NH*NT*KH];     // decay matrix W[h][t][u] hi (A of wkv)
__device__ uint32_t g_WWl [NH*NT*KH];     // decay matrix lo
__device__ uint32_t g_kvTh[NB*NH*64*KH];  // kv^T [bh][c][u-pairs] rounded fp16

// ---------------- helpers -----------------------------------------------------
__device__ __forceinline__ uint32_t pack2h(float a, float b) {
    __half ha = __float2half_rn(a), hb = __float2half_rn(b);
    return (uint32_t)__half_as_ushort(ha) | ((uint32_t)__half_as_ushort(hb) << 16);
}

__device__ __forceinline__ void split2h(float a, float b, uint32_t& hi, uint32_t& lo) {
    __half ha = __float2half_rn(a), hb = __float2half_rn(b);
    float fa = __half2float(ha), fb = __half2float(hb);
    __half la = __float2half_rn(a - fa), lb = __float2half_rn(b - fb);
    hi = (uint32_t)__half_as_ushort(ha) | ((uint32_t)__half_as_ushort(hb) << 16);
    lo = (uint32_t)__half_as_ushort(la) | ((uint32_t)__half_as_ushort(lb) << 16);
}

__device__ __forceinline__ void mma_f16(float* c, const uint32_t* a,
                                        uint32_t b0, uint32_t b1) {
    asm volatile(
        "mma.sync.aligned.m16n8k16.row.col.f32.f16.f16.f32 "
        "{%0,%1,%2,%3},{%4,%5,%6,%7},{%8,%9},{%0,%1,%2,%3};"
        : "+f"(c[0]), "+f"(c[1]), "+f"(c[2]), "+f"(c[3])
        : "r"(a[0]), "r"(a[1]), "r"(a[2]), "r"(a[3]), "r"(b0), "r"(b1));
}

// f16-accumulator MMA (2x rate): D/C are 2 regs holding 4 halves
__device__ __forceinline__ void mma_f16acc(uint32_t* c, const uint32_t* a,
                                           uint32_t b0, uint32_t b1) {
    asm volatile(
        "mma.sync.aligned.m16n8k16.row.col.f16.f16.f16.f16 "
        "{%0,%1},{%2,%3,%4,%5},{%6,%7},{%0,%1};"
        : "+r"(c[0]), "+r"(c[1])
        : "r"(a[0]), "r"(a[1]), "r"(a[2]), "r"(a[3]), "r"(b0), "r"(b1));
}

__device__ __forceinline__ void ldm_x4(uint32_t* r, uint32_t addr) {
    asm volatile("ldmatrix.sync.aligned.m8n8.x4.shared.b16 {%0,%1,%2,%3}, [%4];"
                 : "=r"(r[0]), "=r"(r[1]), "=r"(r[2]), "=r"(r[3]) : "r"(addr));
}

__device__ __forceinline__ void cpa16(uint32_t d, const void* s) {
    asm volatile("cp.async.cg.shared.global [%0], [%1], 16;" :: "r"(d), "l"(s));
}
#define CP_COMMIT() asm volatile("cp.async.commit_group;")
#define CP_WAIT1()  asm volatile("cp.async.wait_group 1;")
#define CP_WAIT0()  asm volatile("cp.async.wait_group 0;")

// merge one f16x2 lo-acc reg into two f32 lanes
__device__ __forceinline__ void merge_lo(float& v0, float& v1, uint32_t packed) {
    __half2 h = *(__half2*)&packed;
    v0 += __half2float(__low2half(h));
    v1 += __half2float(__high2half(h));
}

// ---------------- weight round: all 4 weights -> fp16 in one launch -----------
__global__ void split_w_all_kernel(const float* __restrict__ W0,
                                   const float* __restrict__ W1,
                                   const float* __restrict__ W2,
                                   const float* __restrict__ W3) {
    int i = blockIdx.x * 256 + threadIdx.x;       // over 4*NC*KH
    int w = i >> 19;                              // NC*KH = 512K
    int j = i & (NC * KH - 1);
    const float* W = (w == 0) ? W0 : (w == 1) ? W1 : (w == 2) ? W2 : W3;
    float2 v = ((const float2*)W)[j];
    g_Wh[i] = pack2h(v.x, v.y);
}

// ---------------- decay matrix precompute (fp16 split, causal tiles only) -----
__global__ void build_W_kernel(const float* __restrict__ tw,
                               const float* __restrict__ alpha) {
    int i = blockIdx.x * 256 + threadIdx.x;       // over NH*NT*KH
    int u = (i & (KH - 1)) * 2;
    int t = (i >> 9) & (NT - 1);
    // tiles with u-block above t-block are never read by wkv: skip write
    if ((u >> 6) > (t >> 6)) return;
    int h = i >> 19;
    float w0 = 0.f, w1 = 0.f;
    if (u <= t)     w0 = tw[h * NT + 1023 - t + u]     * alpha[h * NT + u];
    if (u + 1 <= t) w1 = tw[h * NT + 1023 - t + u + 1] * alpha[h * NT + u + 1];
    split2h(w0, w1, g_WWh[i], g_WWl[i]);
}

// ---------------- time-shift + fp16 split --------------------------------------
__global__ void build_xs_split_kernel(const float* __restrict__ x) {
    int i = blockIdx.x * 256 + threadIdx.x;       // over NM*KH
    int kk2 = i & (KH - 1);
    int row = i >> 9;
    int t = row & (NT - 1);
    int c = kk2 * 2;
    float a = 0.f, b = 0.f;
    if (c < NC / 2) {
        if (t != 0) {
            float2 v = *(const float2*)(x + (size_t)(row - 1) * NC + c);
            a = v.x; b = v.y;
        }
    } else {
        float2 v = *(const float2*)(x + (size_t)row * NC + c);
        a = v.x; b = v.y;
    }
    split2h(a, b, g_Ah[i], g_Al[i]);
}

// ---------------- cumsum phase A: per-segment local scans ---------------------
__global__ void cumsumA_kernel() {
    int c = blockIdx.x * 256 + threadIdx.x;
    int b = blockIdx.y, s = blockIdx.z;
    const float* src = g_kvr  + ((size_t)(b * NT + s * TSEG)) * NC + c;
    float*       dst = g_sumk + ((size_t)(b * NT + s * TSEG)) * NC + c;
    float acc = 0.f;
    for (int t0 = 0; t0 < TSEG; t0 += 16) {
        float buf[16];
#pragma unroll
        for (int j = 0; j < 16; j++) buf[j] = src[(size_t)(t0 + j) * NC];
#pragma unroll
        for (int j = 0; j < 16; j++) { acc += buf[j]; dst[(size_t)(t0 + j) * NC] = acc; }
    }
    g_segtot[(b * NSEG + s) * NC + c] = acc;
}

// ---------------- cumsum phase B: exclusive scan of segment totals ------------
__global__ void segscan_kernel() {
    int c = blockIdx.x * 256 + threadIdx.x;
    int b = blockIdx.y;
    float s = 0.f;
#pragma unroll
    for (int seg = 0; seg < NSEG; seg++) {
        g_segoff[(b * NSEG + seg) * NC + c] = s;
        s += g_segtot[(b * NSEG + seg) * NC + c];
    }
}

// ---------------- rwkv = sigmoid(r)*wkv/(local+offset), then fp16 split -------
__global__ void rwkv_split_kernel() {
    int i = blockIdx.x * 256 + threadIdx.x;       // over NM*KH
    int j = i * 2;
    int row = i >> 9;
    int t = row & (NT - 1);
    int b = row >> 10;
    int c = (i & (KH - 1)) * 2;
    int so = (b * NSEG + (t >> 7)) * NC + c;
    const float* rr = g_kvr + 2 * (size_t)NM * NC;
    float r0 = rr[j], r1 = rr[j + 1];
    float s0 = g_sumk[j]     + g_segoff[so];
    float s1 = g_sumk[j + 1] + g_segoff[so + 1];
    float a = (1.f / (1.f + expf(-r0))) * g_wkv[j]     / s0;
    float bq = (1.f / (1.f + expf(-r1))) * g_wkv[j + 1] / s1;
    split2h(a, bq, g_Ah[i], g_Al[i]);
}

// ---------------- kv^T: round to fp16 (B operand of wkv) ----------------------
__global__ void kvt_split_kernel() {
    __shared__ float skv[64][65];
    int ut = blockIdx.x;
    int bh = blockIdx.y;
    int b = bh >> 4, h = bh & 15;
    int tid = threadIdx.x;
    int u0 = ut * 64;
    const float* kb = g_kvr + ((size_t)(b * NT + u0)) * NC + h * 64;
    const float* vb = g_kvr + (size_t)NM * NC + ((size_t)(b * NT + u0)) * NC + h * 64;
#pragma unroll
    for (int rr = 0; rr < 16; rr++) {
        int i = tid + rr * 256;
        int uu = i >> 6, c = i & 63;
        skv[uu][c] = kb[(size_t)uu * NC + c] * vb[(size_t)uu * NC + c];
    }
    __syncthreads();
    uint32_t* oh = g_kvTh + (size_t)bh * 64 * KH + ut * 32;
#pragma unroll
    for (int rr = 0; rr < 8; rr++) {
        int j = tid + rr * 256;
        int c = j >> 5, g = j & 31;
        oh[(size_t)c * KH + g] = pack2h(skv[g * 2][c], skv[g * 2 + 1][c]);
    }
}

// ---------------- wkv via tensor cores (fp16x2, causal, 3-stage pipe) ----------
// Regions (3 stages each): [WWh | WWl | Kh]
#define WR 20
#define WST (64*WR)

__global__ void __launch_bounds__(256) wkv_mma_kernel(const float* __restrict__ beta) {
    __shared__ uint32_t smw[9 * WST];       // 45KB
    int tt = blockIdx.x, bh = blockIdx.y;
    int b = bh >> 4, h = bh & 15;
    int t0 = tt * 64;
    int tid = threadIdx.x;
    int lrow = tid >> 2, lq = (tid & 3) * 4;

    const uint32_t* pWh = g_WWh + ((size_t)h * NT + t0 + lrow) * KH + lq;
    const uint32_t* pWl = g_WWl + ((size_t)h * NT + t0 + lrow) * KH + lq;
    const uint32_t* pKh = g_kvTh + ((size_t)bh * 64 + lrow) * KH + lq;
    uint32_t smw_b = (uint32_t)__cvta_generic_to_shared(smw);
    uint32_t sb = smw_b + (lrow * WR + lq) * 4;

    int lane = tid & 31, warp = tid >> 5;
    int wm = (warp >> 1) * 16, wn = (warp & 1) * 32;
    int r = lane >> 2, cc = lane & 3;

    int a_base = (wm + (lane & 15)) * WR + (lane >> 4) * 4;
    int b_base = (wn + ((lane >> 4) << 3) + (lane & 7)) * WR + ((lane >> 3) & 1) * 4;

    float acc[4][4];
    uint32_t accl[4][2];
#pragma unroll
    for (int i = 0; i < 4; i++) {
#pragma unroll
        for (int j = 0; j < 4; j++) acc[i][j] = 0.f;
        accl[i][0] = 0u; accl[i][1] = 0u;
    }

    int nut = 2 * (tt + 1);     // >= 2

#pragma unroll
    for (int s = 0; s < 2; s++) {
        uint32_t d = sb + s * WST * 4;
        int o = s * 16;
        cpa16(d,               pWh + o);
        cpa16(d + 3 * WST * 4, pWl + o);
        cpa16(d + 6 * WST * 4, pKh + o);
        CP_COMMIT();
    }

    for (int ut = 0; ut < nut; ut++) {
        if (ut + 1 < nut) CP_WAIT1(); else CP_WAIT0();
        __syncthreads();
        if (ut + 2 < nut) {
            int slot = (ut + 2) % 3;
            uint32_t d = sb + slot * WST * 4;
            int o = (ut + 2) * 16;
            cpa16(d,               pWh + o);
            cpa16(d + 3 * WST * 4, pWl + o);
            cpa16(d + 6 * WST * 4, pKh + o);
            CP_COMMIT();
        }

        uint32_t stoff = (ut % 3) * WST;
#pragma unroll
        for (int ks = 0; ks < 2; ks++) {
            uint32_t ah[4], al[4];
            uint32_t ai = smw_b + (stoff + a_base + ks * 8) * 4;
            ldm_x4(ah, ai);
            ldm_x4(al, ai + 3 * WST * 4);
#pragma unroll
            for (int jp = 0; jp < 2; jp++) {
                uint32_t bb[4];
                uint32_t bi = smw_b + (stoff + b_base + jp * 16 * WR + ks * 8) * 4;
                ldm_x4(bb, bi + 6 * WST * 4);
#pragma unroll
                for (int hf = 0; hf < 2; hf++)
                    mma_f16(acc[jp * 2 + hf], ah, bb[hf * 2], bb[hf * 2 + 1]);
#pragma unroll
                for (int hf = 0; hf < 2; hf++)
                    mma_f16acc(accl[jp * 2 + hf], al, bb[hf * 2], bb[hf * 2 + 1]);
            }
        }
    }

    int tlo = t0 + wm + r, thi = tlo + 8;
    float be_lo = beta[h * NT + tlo], be_hi = beta[h * NT + thi];
    float* orow_lo = g_wkv + ((size_t)(b * NT + tlo)) * NC + h * 64;
    float* orow_hi = g_wkv + ((size_t)(b * NT + thi)) * NC + h * 64;
#pragma unroll
    for (int nj = 0; nj < 4; nj++) {
        float v0 = acc[nj][0], v1 = acc[nj][1], v2 = acc[nj][2], v3 = acc[nj][3];
        merge_lo(v0, v1, accl[nj][0]);
        merge_lo(v2, v3, accl[nj][1]);
        int col = wn + nj * 8 + cc * 2;
        float2 o1 = {v0 * be_lo, v1 * be_lo};
        float2 o2 = {v2 * be_hi, v3 * be_hi};
        *(float2*)&orow_lo[col] = o1;
        *(float2*)&orow_hi[col] = o2;
    }
}

// ---------------- fp16x2 GEMM, K-tile 32, 3-stage pipe, f16-acc lo term -------
// MODE 0: grid (64,24); sel=by>>3 picks {Wk,Wv,Wr}; exp epilogue for sel==0.
// MODE 1: grid (64,8); weight slab 3 (Wo); bias bo; *gamma[t] epilogue.
#define RS 20                  // row stride in u32 (16 data + 4 pad)
#define WS (128*RS)            // u32 per region per stage

template<int MODE>
__global__ void __launch_bounds__(256, 2) gemm_f16x2_k32(
    const uint32_t* __restrict__ Ah, const uint32_t* __restrict__ Al,
    float* __restrict__ Cout,
    const float* __restrict__ b0p, const float* __restrict__ b1p,
    const float* __restrict__ b2p, const float* __restrict__ gamma)
{
    extern __shared__ uint32_t sm[];   // [Ah:3][Al:3][Bh:3] stages
    int tid = threadIdx.x;
    int m0 = blockIdx.x * 128;
    int sel, n0;
    const float* bias;
    float* C;
    if (MODE == 0) {
        sel = blockIdx.y >> 3;
        n0 = (blockIdx.y & 7) * 128;
        bias = (sel == 0) ? b0p : (sel == 1) ? b1p : b2p;
        C = Cout + (size_t)sel * NM * NC;
    } else {
        sel = 3;
        n0 = blockIdx.y * 128;
        bias = b0p;
        C = Cout;
    }
    const uint32_t* Bh = g_Wh + (size_t)sel * NC * KH;

    int lrow = tid >> 1;
    int lg = (tid & 1) * 8;
    const uint32_t* pAh = Ah + (size_t)(m0 + lrow) * KH + lg;
    const uint32_t* pAl = Al + (size_t)(m0 + lrow) * KH + lg;
    const uint32_t* pBh = Bh + (size_t)(n0 + lrow) * KH + lg;
    uint32_t smem_b = (uint32_t)__cvta_generic_to_shared(sm);
    uint32_t sbase = smem_b + (lrow * RS + lg) * 4;

    int lane = tid & 31, warp = tid >> 5;
    int wm = (warp >> 1) * 32, wn = (warp & 1) * 64;
    int r = lane >> 2, cc = lane & 3;

    int a_base = (wm + (lane & 15)) * RS + (lane >> 4) * 4;
    int b_base = (wn + ((lane >> 4) << 3) + (lane & 7)) * RS + ((lane >> 3) & 1) * 4;

    float acc[2][8][4];
    uint32_t accl[2][8][2];
#pragma unroll
    for (int a = 0; a < 2; a++)
#pragma unroll
        for (int b = 0; b < 8; b++) {
#pragma unroll
            for (int q = 0; q < 4; q++) acc[a][b][q] = 0.f;
            accl[a][b][0] = 0u; accl[a][b][1] = 0u;
        }

#pragma unroll
    for (int s = 0; s < 2; s++) {
        uint32_t d = sbase + s * WS * 4;
        int o = s * 16;
        cpa16(d,              pAh + o);  cpa16(d + 16,              pAh + o + 4);
        cpa16(d + 3*WS*4,     pAl + o);  cpa16(d + 3*WS*4 + 16,     pAl + o + 4);
        cpa16(d + 6*WS*4,     pBh + o);  cpa16(d + 6*WS*4 + 16,     pBh + o + 4);
        CP_COMMIT();
    }

    for (int kt = 0; kt < 32; kt++) {
        if (kt + 1 < 32) CP_WAIT1(); else CP_WAIT0();
        __syncthreads();
        if (kt + 2 < 32) {
            int slot = (kt + 2) % 3;
            uint32_t d = sbase + slot * WS * 4;
            int o = (kt + 2) * 16;
            cpa16(d,              pAh + o);  cpa16(d + 16,              pAh + o + 4);
            cpa16(d + 3*WS*4,     pAl + o);  cpa16(d + 3*WS*4 + 16,     pAl + o + 4);
            cpa16(d + 6*WS*4,     pBh + o);  cpa16(d + 6*WS*4 + 16,     pBh + o + 4);
            CP_COMMIT();
        }

        uint32_t st = (kt % 3) * WS;
#pragma unroll
        for (int ks = 0; ks < 2; ks++) {
            uint32_t ah[2][4], al[2][4];
#pragma unroll
            for (int mi = 0; mi < 2; mi++) {
                uint32_t ai = smem_b + (st + a_base + mi * 16 * RS + ks * 8) * 4;
                ldm_x4(ah[mi], ai);
                ldm_x4(al[mi], ai + 3 * WS * 4);
            }
#pragma unroll
            for (int jp = 0; jp < 4; jp++) {
                uint32_t bb[4];
                uint32_t bi = smem_b + (st + b_base + jp * 16 * RS + ks * 8) * 4;
                ldm_x4(bb, bi + 6 * WS * 4);
                // hh term: f32 acc (8 independent MMAs)
#pragma unroll
                for (int hf = 0; hf < 2; hf++)
#pragma unroll
                    for (int mi = 0; mi < 2; mi++)
                        mma_f16(acc[mi][jp * 2 + hf], ah[mi], bb[hf * 2], bb[hf * 2 + 1]);
                // lh term: f16 acc (2x rate)
#pragma unroll
                for (int hf = 0; hf < 2; hf++)
#pragma unroll
                    for (int mi = 0; mi < 2; mi++)
                        mma_f16acc(accl[mi][jp * 2 + hf], al[mi], bb[hf * 2], bb[hf * 2 + 1]);
            }
        }
    }

#pragma unroll
    for (int mi = 0; mi < 2; mi++) {
        int mlo = m0 + wm + mi * 16 + r;
        int mhi = mlo + 8;
        float glo = 1.f, ghi = 1.f;
        if (MODE == 1) { glo = gamma[mlo & (NT - 1)]; ghi = gamma[mhi & (NT - 1)]; }
#pragma unroll
        for (int nj = 0; nj < 8; nj++) {
            int col = n0 + wn + nj * 8 + cc * 2;
            float b0 = bias[col], b1 = bias[col + 1];
            float v0 = acc[mi][nj][0], v1 = acc[mi][nj][1];
            float v2 = acc[mi][nj][2], v3 = acc[mi][nj][3];
            merge_lo(v0, v1, accl[mi][nj][0]);
            merge_lo(v2, v3, accl[mi][nj][1]);
            v0 += b0; v1 += b1; v2 += b0; v3 += b1;
            if (MODE == 0) {
                if (sel == 0) {
                    v0 = expf(fminf(fmaxf(v0, -60.f), 30.f));
                    v1 = expf(fminf(fmaxf(v1, -60.f), 30.f));
                    v2 = expf(fminf(fmaxf(v2, -60.f), 30.f));
                    v3 = expf(fminf(fmaxf(v3, -60.f), 30.f));
                }
            } else {
                v0 *= glo; v1 *= glo; v2 *= ghi; v3 *= ghi;
            }
            float2 o01 = {v0, v1}, o23 = {v2, v3};
            *(float2*)&C[(size_t)mlo * NC + col] = o01;
            *(float2*)&C[(size_t)mhi * NC + col] = o23;
        }
    }
}

// ---------------- host launch -------------------------------------------------
extern "C" void kernel_launch(void* const* d_in, const int* in_sizes, int n_in,
                              void* d_out, int out_size) {
    (void)in_sizes; (void)n_in; (void)out_size;
    const float* x      = (const float*)d_in[0];
    const float* time_w = (const float*)d_in[1];
    const float* alpha  = (const float*)d_in[2];
    const float* beta   = (const float*)d_in[3];
    const float* gamma  = (const float*)d_in[4];
    const float* Wk = (const float*)d_in[5];
    const float* bk = (const float*)d_in[6];
    const float* Wv = (const float*)d_in[7];
    const float* bv = (const float*)d_in[8];
    const float* Wr = (const float*)d_in[9];
    const float* br = (const float*)d_in[10];
    const float* Wo = (const float*)d_in[11];
    const float* bo = (const float*)d_in[12];
    float* out = (float*)d_out;

    float *kvr;
    uint32_t *Ah, *Al;
    cudaGetSymbolAddress((void**)&kvr, g_kvr);
    cudaGetSymbolAddress((void**)&Ah,  g_Ah);
    cudaGetSymbolAddress((void**)&Al,  g_Al);

    size_t smem = 9 * WS * 4;   // 90KB (3 regions x 3 stages)
    static int attr_set = 0;
    if (!attr_set) {
        cudaFuncSetAttribute(gemm_f16x2_k32<0>,
                             cudaFuncAttributeMaxDynamicSharedMemorySize, (int)smem);
        cudaFuncSetAttribute(gemm_f16x2_k32<1>,
                             cudaFuncAttributeMaxDynamicSharedMemorySize, (int)smem);
        attr_set = 1;
    }

    split_w_all_kernel<<<4 * NC * KH / 256, 256>>>(Wk, Wv, Wr, Wo);
    build_W_kernel<<<NH * NT * KH / 256, 256>>>(time_w, alpha);
    build_xs_split_kernel<<<NM * KH / 256, 256>>>(x);

    gemm_f16x2_k32<0><<<dim3(NM / 128, 24), 256, smem>>>(Ah, Al, kvr, bk, bv, br, nullptr);

    cumsumA_kernel<<<dim3(NC / 256, NB, NSEG), 256>>>();
    segscan_kernel<<<dim3(NC / 256, NB), 256>>>();

    kvt_split_kernel<<<dim3(NT / 64, NB * NH), 256>>>();
    wkv_mma_kernel<<<dim3(NT / 64, NB * NH), 256>>>(beta);

    rwkv_split_kernel<<<NM * KH / 256, 256>>>();

    gemm_f16x2_k32<1><<<dim3(NM / 128, 8), 256, smem>>>(Ah, Al, out, bo, nullptr, nullptr, gamma);
}

// round 11
// speedup vs baseline: 1.2419x; 1.2419x over previous
#include <cuda_runtime.h>
#include <cuda_fp16.h>
#include <math.h>
#include <stdint.h>

#define NB 8
#define NT 1024
#define NC 1024
#define NH 16
#define NM (NB*NT)
#define KH 512            // K/2 (fp16 pairs packed along K)
#define NSEG 8
#define TSEG (NT/NSEG)

// ---------------- scratch (static device globals, no allocation) -------------
__device__ float    g_kvr [3*NM*NC];      // k, v, r
__device__ float    g_sumk[NM*NC];        // per-segment local cumsum
__device__ float    g_segtot[NB*NSEG*NC];
__device__ float    g_segoff[NB*NSEG*NC];
__device__ float    g_wkv [NM*NC];
__device__ uint32_t g_Ah  [NM*KH];        // packed f16x2 hi of current A operand
__device__ uint32_t g_Al  [NM*KH];        // packed f16x2 lo
__device__ uint32_t g_Wh  [4*NC*KH];      // Wk,Wv,Wr,Wo rounded to fp16 (B operand)
__device__ uint32_t g_WWh [NH*NT*KH];     // decay matrix W[h][t][u] hi (A of wkv)
__device__ uint32_t g_WWl [NH*NT*KH];     // decay matrix lo
__device__ uint32_t g_kvTh[NB*NH*64*KH];  // kv^T [bh][c][u-pairs] rounded fp16

// ---------------- helpers -----------------------------------------------------
__device__ __forceinline__ uint32_t pack2h(float a, float b) {
    __half ha = __float2half_rn(a), hb = __float2half_rn(b);
    return (uint32_t)__half_as_ushort(ha) | ((uint32_t)__half_as_ushort(hb) << 16);
}

__device__ __forceinline__ void split2h(float a, float b, uint32_t& hi, uint32_t& lo) {
    __half ha = __float2half_rn(a), hb = __float2half_rn(b);
    float fa = __half2float(ha), fb = __half2float(hb);
    __half la = __float2half_rn(a - fa), lb = __float2half_rn(b - fb);
    hi = (uint32_t)__half_as_ushort(ha) | ((uint32_t)__half_as_ushort(hb) << 16);
    lo = (uint32_t)__half_as_ushort(la) | ((uint32_t)__half_as_ushort(lb) << 16);
}

__device__ __forceinline__ void mma_f16(float* c, const uint32_t* a,
                                        uint32_t b0, uint32_t b1) {
    asm volatile(
        "mma.sync.aligned.m16n8k16.row.col.f32.f16.f16.f32 "
        "{%0,%1,%2,%3},{%4,%5,%6,%7},{%8,%9},{%0,%1,%2,%3};"
        : "+f"(c[0]), "+f"(c[1]), "+f"(c[2]), "+f"(c[3])
        : "r"(a[0]), "r"(a[1]), "r"(a[2]), "r"(a[3]), "r"(b0), "r"(b1));
}

__device__ __forceinline__ void ldm_x4(uint32_t* r, uint32_t addr) {
    asm volatile("ldmatrix.sync.aligned.m8n8.x4.shared.b16 {%0,%1,%2,%3}, [%4];"
                 : "=r"(r[0]), "=r"(r[1]), "=r"(r[2]), "=r"(r[3]) : "r"(addr));
}

__device__ __forceinline__ void cpa16(uint32_t d, const void* s) {
    asm volatile("cp.async.cg.shared.global [%0], [%1], 16;" :: "r"(d), "l"(s));
}
#define CP_COMMIT() asm volatile("cp.async.commit_group;")
#define CP_WAIT1()  asm volatile("cp.async.wait_group 1;")
#define CP_WAIT0()  asm volatile("cp.async.wait_group 0;")

// ---------------- weight round: all 4 weights -> fp16 in one launch -----------
__global__ void split_w_all_kernel(const float* __restrict__ W0,
                                   const float* __restrict__ W1,
                                   const float* __restrict__ W2,
                                   const float* __restrict__ W3) {
    int i = blockIdx.x * 256 + threadIdx.x;       // over 4*NC*KH
    int w = i >> 19;                              // NC*KH = 512K
    int j = i & (NC * KH - 1);
    const float* W = (w == 0) ? W0 : (w == 1) ? W1 : (w == 2) ? W2 : W3;
    float2 v = ((const float2*)W)[j];
    g_Wh[i] = pack2h(v.x, v.y);
}

// ---------------- decay matrix precompute (fp16 split, causal tiles only) -----
__global__ void build_W_kernel(const float* __restrict__ tw,
                               const float* __restrict__ alpha) {
    int i = blockIdx.x * 256 + threadIdx.x;       // over NH*NT*KH
    int u = (i & (KH - 1)) * 2;
    int t = (i >> 9) & (NT - 1);
    // tiles with u-block above t-block are never read by wkv: skip write
    if ((u >> 6) > (t >> 6)) return;
    int h = i >> 19;
    float w0 = 0.f, w1 = 0.f;
    if (u <= t)     w0 = tw[h * NT + 1023 - t + u]     * alpha[h * NT + u];
    if (u + 1 <= t) w1 = tw[h * NT + 1023 - t + u + 1] * alpha[h * NT + u + 1];
    split2h(w0, w1, g_WWh[i], g_WWl[i]);
}

// ---------------- time-shift + fp16 split --------------------------------------
__global__ void build_xs_split_kernel(const float* __restrict__ x) {
    int i = blockIdx.x * 256 + threadIdx.x;       // over NM*KH
    int kk2 = i & (KH - 1);
    int row = i >> 9;
    int t = row & (NT - 1);
    int c = kk2 * 2;
    float a = 0.f, b = 0.f;
    if (c < NC / 2) {
        if (t != 0) {
            float2 v = *(const float2*)(x + (size_t)(row - 1) * NC + c);
            a = v.x; b = v.y;
        }
    } else {
        float2 v = *(const float2*)(x + (size_t)row * NC + c);
        a = v.x; b = v.y;
    }
    split2h(a, b, g_Ah[i], g_Al[i]);
}

// ---------------- cumsum phase A: per-segment local scans ---------------------
__global__ void cumsumA_kernel() {
    int c = blockIdx.x * 256 + threadIdx.x;
    int b = blockIdx.y, s = blockIdx.z;
    const float* src = g_kvr  + ((size_t)(b * NT + s * TSEG)) * NC + c;
    float*       dst = g_sumk + ((size_t)(b * NT + s * TSEG)) * NC + c;
    float acc = 0.f;
    for (int t0 = 0; t0 < TSEG; t0 += 16) {
        float buf[16];
#pragma unroll
        for (int j = 0; j < 16; j++) buf[j] = src[(size_t)(t0 + j) * NC];
#pragma unroll
        for (int j = 0; j < 16; j++) { acc += buf[j]; dst[(size_t)(t0 + j) * NC] = acc; }
    }
    g_segtot[(b * NSEG + s) * NC + c] = acc;
}

// ---------------- cumsum phase B: exclusive scan of segment totals ------------
__global__ void segscan_kernel() {
    int c = blockIdx.x * 256 + threadIdx.x;
    int b = blockIdx.y;
    float s = 0.f;
#pragma unroll
    for (int seg = 0; seg < NSEG; seg++) {
        g_segoff[(b * NSEG + seg) * NC + c] = s;
        s += g_segtot[(b * NSEG + seg) * NC + c];
    }
}

// ---------------- rwkv = sigmoid(r)*wkv/(local+offset), then fp16 split -------
__global__ void rwkv_split_kernel() {
    int i = blockIdx.x * 256 + threadIdx.x;       // over NM*KH
    int j = i * 2;
    int row = i >> 9;
    int t = row & (NT - 1);
    int b = row >> 10;
    int c = (i & (KH - 1)) * 2;
    int so = (b * NSEG + (t >> 7)) * NC + c;
    const float* rr = g_kvr + 2 * (size_t)NM * NC;
    float r0 = rr[j], r1 = rr[j + 1];
    float s0 = g_sumk[j]     + g_segoff[so];
    float s1 = g_sumk[j + 1] + g_segoff[so + 1];
    float a = (1.f / (1.f + expf(-r0))) * g_wkv[j]     / s0;
    float bq = (1.f / (1.f + expf(-r1))) * g_wkv[j + 1] / s1;
    split2h(a, bq, g_Ah[i], g_Al[i]);
}

// ---------------- kv^T: round to fp16 (B operand of wkv) ----------------------
__global__ void kvt_split_kernel() {
    __shared__ float skv[64][65];
    int ut = blockIdx.x;
    int bh = blockIdx.y;
    int b = bh >> 4, h = bh & 15;
    int tid = threadIdx.x;
    int u0 = ut * 64;
    const float* kb = g_kvr + ((size_t)(b * NT + u0)) * NC + h * 64;
    const float* vb = g_kvr + (size_t)NM * NC + ((size_t)(b * NT + u0)) * NC + h * 64;
#pragma unroll
    for (int rr = 0; rr < 16; rr++) {
        int i = tid + rr * 256;
        int uu = i >> 6, c = i & 63;
        skv[uu][c] = kb[(size_t)uu * NC + c] * vb[(size_t)uu * NC + c];
    }
    __syncthreads();
    uint32_t* oh = g_kvTh + (size_t)bh * 64 * KH + ut * 32;
#pragma unroll
    for (int rr = 0; rr < 8; rr++) {
        int j = tid + rr * 256;
        int c = j >> 5, g = j & 31;
        oh[(size_t)c * KH + g] = pack2h(skv[g * 2][c], skv[g * 2 + 1][c]);
    }
}

// ---------------- wkv via tensor cores (fp16x2, causal, 3-stage pipe) ----------
// Regions (3 stages each): [WWh | WWl | Kh]
#define WR 20
#define WST (64*WR)

__global__ void __launch_bounds__(256) wkv_mma_kernel(const float* __restrict__ beta) {
    __shared__ uint32_t smw[9 * WST];       // 45KB
    int tt = blockIdx.x, bh = blockIdx.y;
    int b = bh >> 4, h = bh & 15;
    int t0 = tt * 64;
    int tid = threadIdx.x;
    int lrow = tid >> 2, lq = (tid & 3) * 4;

    const uint32_t* pWh = g_WWh + ((size_t)h * NT + t0 + lrow) * KH + lq;
    const uint32_t* pWl = g_WWl + ((size_t)h * NT + t0 + lrow) * KH + lq;
    const uint32_t* pKh = g_kvTh + ((size_t)bh * 64 + lrow) * KH + lq;
    uint32_t smw_b = (uint32_t)__cvta_generic_to_shared(smw);
    uint32_t sb = smw_b + (lrow * WR + lq) * 4;

    int lane = tid & 31, warp = tid >> 5;
    int wm = (warp >> 1) * 16, wn = (warp & 1) * 32;
    int r = lane >> 2, cc = lane & 3;

    int a_base = (wm + (lane & 15)) * WR + (lane >> 4) * 4;
    int b_base = (wn + ((lane >> 4) << 3) + (lane & 7)) * WR + ((lane >> 3) & 1) * 4;

    float acc[4][4];
#pragma unroll
    for (int i = 0; i < 4; i++)
#pragma unroll
        for (int j = 0; j < 4; j++) acc[i][j] = 0.f;

    int nut = 2 * (tt + 1);     // >= 2

#pragma unroll
    for (int s = 0; s < 2; s++) {
        uint32_t d = sb + s * WST * 4;
        int o = s * 16;
        cpa16(d,               pWh + o);
        cpa16(d + 3 * WST * 4, pWl + o);
        cpa16(d + 6 * WST * 4, pKh + o);
        CP_COMMIT();
    }

    for (int ut = 0; ut < nut; ut++) {
        if (ut + 1 < nut) CP_WAIT1(); else CP_WAIT0();
        __syncthreads();
        if (ut + 2 < nut) {
            int slot = (ut + 2) % 3;
            uint32_t d = sb + slot * WST * 4;
            int o = (ut + 2) * 16;
            cpa16(d,               pWh + o);
            cpa16(d + 3 * WST * 4, pWl + o);
            cpa16(d + 6 * WST * 4, pKh + o);
            CP_COMMIT();
        }

        uint32_t stoff = (ut % 3) * WST;
#pragma unroll
        for (int ks = 0; ks < 2; ks++) {
            uint32_t ah[4], al[4];
            uint32_t ai = smw_b + (stoff + a_base + ks * 8) * 4;
            ldm_x4(ah, ai);
            ldm_x4(al, ai + 3 * WST * 4);

            uint32_t bhf[2][4];
#pragma unroll
            for (int jp = 0; jp < 2; jp++) {
                uint32_t bi = smw_b + (stoff + b_base + jp * 16 * WR + ks * 8) * 4;
                ldm_x4(bhf[jp], bi + 6 * WST * 4);
            }
#pragma unroll
            for (int jp = 0; jp < 2; jp++)
#pragma unroll
                for (int hf = 0; hf < 2; hf++)
                    mma_f16(acc[jp * 2 + hf], ah, bhf[jp][hf * 2], bhf[jp][hf * 2 + 1]);
#pragma unroll
            for (int jp = 0; jp < 2; jp++)
#pragma unroll
                for (int hf = 0; hf < 2; hf++)
                    mma_f16(acc[jp * 2 + hf], al, bhf[jp][hf * 2], bhf[jp][hf * 2 + 1]);
        }
    }

    int tlo = t0 + wm + r, thi = tlo + 8;
    float be_lo = beta[h * NT + tlo], be_hi = beta[h * NT + thi];
    float* orow_lo = g_wkv + ((size_t)(b * NT + tlo)) * NC + h * 64;
    float* orow_hi = g_wkv + ((size_t)(b * NT + thi)) * NC + h * 64;
#pragma unroll
    for (int nj = 0; nj < 4; nj++) {
        int col = wn + nj * 8 + cc * 2;
        float2 o1 = {acc[nj][0] * be_lo, acc[nj][1] * be_lo};
        float2 o2 = {acc[nj][2] * be_hi, acc[nj][3] * be_hi};
        *(float2*)&orow_lo[col] = o1;
        *(float2*)&orow_hi[col] = o2;
    }
}

// ---------------- fp16x2 GEMM, K-tile 32, 3-stage pipe, selective lo term -----
// MODE 0: grid (64,24); sel=by>>3 picks {Wk,Wv,Wr}; exp epilogue for sel==0.
//         lo (A residual) term computed ONLY for sel==1 (v) — k and r tolerate
//         single-fp16 A (exp-ratio cancellation / sigmoid damping).
// MODE 1: grid (64,8); weight slab 3 (Wo); bias bo; *gamma[t] epilogue; lo on.
#define RS 20                  // row stride in u32 (16 data + 4 pad)
#define WS (128*RS)            // u32 per region per stage

template<int MODE>
__global__ void __launch_bounds__(256, 2) gemm_f16x2_k32(
    const uint32_t* __restrict__ Ah, const uint32_t* __restrict__ Al,
    float* __restrict__ Cout,
    const float* __restrict__ b0p, const float* __restrict__ b1p,
    const float* __restrict__ b2p, const float* __restrict__ gamma)
{
    extern __shared__ uint32_t sm[];   // [Ah:3][Al:3][Bh:3] stages
    int tid = threadIdx.x;
    int m0 = blockIdx.x * 128;
    int sel, n0;
    const float* bias;
    float* C;
    if (MODE == 0) {
        sel = blockIdx.y >> 3;
        n0 = (blockIdx.y & 7) * 128;
        bias = (sel == 0) ? b0p : (sel == 1) ? b1p : b2p;
        C = Cout + (size_t)sel * NM * NC;
    } else {
        sel = 3;
        n0 = blockIdx.y * 128;
        bias = b0p;
        C = Cout;
    }
    const bool lo_on = (MODE == 1) || (sel == 1);
    const uint32_t* Bh = g_Wh + (size_t)sel * NC * KH;

    int lrow = tid >> 1;
    int lg = (tid & 1) * 8;
    const uint32_t* pAh = Ah + (size_t)(m0 + lrow) * KH + lg;
    const uint32_t* pAl = Al + (size_t)(m0 + lrow) * KH + lg;
    const uint32_t* pBh = Bh + (size_t)(n0 + lrow) * KH + lg;
    uint32_t smem_b = (uint32_t)__cvta_generic_to_shared(sm);
    uint32_t sbase = smem_b + (lrow * RS + lg) * 4;

    int lane = tid & 31, warp = tid >> 5;
    int wm = (warp >> 1) * 32, wn = (warp & 1) * 64;
    int r = lane >> 2, cc = lane & 3;

    int a_base = (wm + (lane & 15)) * RS + (lane >> 4) * 4;
    int b_base = (wn + ((lane >> 4) << 3) + (lane & 7)) * RS + ((lane >> 3) & 1) * 4;

    float acc[2][8][4];
#pragma unroll
    for (int a = 0; a < 2; a++)
#pragma unroll
        for (int b = 0; b < 8; b++)
#pragma unroll
            for (int q = 0; q < 4; q++) acc[a][b][q] = 0.f;

    // prologue: stages 0, 1
#pragma unroll
    for (int s = 0; s < 2; s++) {
        uint32_t d = sbase + s * WS * 4;
        int o = s * 16;
        cpa16(d,              pAh + o);  cpa16(d + 16,              pAh + o + 4);
        if (lo_on) {
            cpa16(d + 3*WS*4, pAl + o);  cpa16(d + 3*WS*4 + 16,     pAl + o + 4);
        }
        cpa16(d + 6*WS*4,     pBh + o);  cpa16(d + 6*WS*4 + 16,     pBh + o + 4);
        CP_COMMIT();
    }

    for (int kt = 0; kt < 32; kt++) {
        if (kt + 1 < 32) CP_WAIT1(); else CP_WAIT0();
        __syncthreads();
        if (kt + 2 < 32) {
            int slot = (kt + 2) % 3;
            uint32_t d = sbase + slot * WS * 4;
            int o = (kt + 2) * 16;
            cpa16(d,              pAh + o);  cpa16(d + 16,              pAh + o + 4);
            if (lo_on) {
                cpa16(d + 3*WS*4, pAl + o);  cpa16(d + 3*WS*4 + 16,     pAl + o + 4);
            }
            cpa16(d + 6*WS*4,     pBh + o);  cpa16(d + 6*WS*4 + 16,     pBh + o + 4);
            CP_COMMIT();
        }

        uint32_t st = (kt % 3) * WS;
#pragma unroll
        for (int ks = 0; ks < 2; ks++) {
            uint32_t ah[2][4], al[2][4];
#pragma unroll
            for (int mi = 0; mi < 2; mi++) {
                uint32_t ai = smem_b + (st + a_base + mi * 16 * RS + ks * 8) * 4;
                ldm_x4(ah[mi], ai);
                if (lo_on) ldm_x4(al[mi], ai + 3 * WS * 4);
            }
#pragma unroll
            for (int jpp = 0; jpp < 2; jpp++) {
                uint32_t bhf[2][4];
#pragma unroll
                for (int q = 0; q < 2; q++) {
                    int jp = jpp * 2 + q;
                    uint32_t bi = smem_b + (st + b_base + jp * 16 * RS + ks * 8) * 4;
                    ldm_x4(bhf[q], bi + 6 * WS * 4);
                }
                // term hh (8 accs)
#pragma unroll
                for (int q = 0; q < 2; q++)
#pragma unroll
                    for (int hf = 0; hf < 2; hf++)
#pragma unroll
                        for (int mi = 0; mi < 2; mi++)
                            mma_f16(acc[mi][(jpp * 2 + q) * 2 + hf], ah[mi],
                                    bhf[q][hf * 2], bhf[q][hf * 2 + 1]);
                // term lh (only when lo_on)
                if (lo_on) {
#pragma unroll
                    for (int q = 0; q < 2; q++)
#pragma unroll
                        for (int hf = 0; hf < 2; hf++)
#pragma unroll
                            for (int mi = 0; mi < 2; mi++)
                                mma_f16(acc[mi][(jpp * 2 + q) * 2 + hf], al[mi],
                                        bhf[q][hf * 2], bhf[q][hf * 2 + 1]);
                }
            }
        }
    }

#pragma unroll
    for (int mi = 0; mi < 2; mi++) {
        int mlo = m0 + wm + mi * 16 + r;
        int mhi = mlo + 8;
        float glo = 1.f, ghi = 1.f;
        if (MODE == 1) { glo = gamma[mlo & (NT - 1)]; ghi = gamma[mhi & (NT - 1)]; }
#pragma unroll
        for (int nj = 0; nj < 8; nj++) {
            int col = n0 + wn + nj * 8 + cc * 2;
            float b0 = bias[col], b1 = bias[col + 1];
            float v0 = acc[mi][nj][0] + b0, v1 = acc[mi][nj][1] + b1;
            float v2 = acc[mi][nj][2] + b0, v3 = acc[mi][nj][3] + b1;
            if (MODE == 0) {
                if (sel == 0) {
                    v0 = expf(fminf(fmaxf(v0, -60.f), 30.f));
                    v1 = expf(fminf(fmaxf(v1, -60.f), 30.f));
                    v2 = expf(fminf(fmaxf(v2, -60.f), 30.f));
                    v3 = expf(fminf(fmaxf(v3, -60.f), 30.f));
                }
            } else {
                v0 *= glo; v1 *= glo; v2 *= ghi; v3 *= ghi;
            }
            float2 o01 = {v0, v1}, o23 = {v2, v3};
            *(float2*)&C[(size_t)mlo * NC + col] = o01;
            *(float2*)&C[(size_t)mhi * NC + col] = o23;
        }
    }
}

// ---------------- host launch -------------------------------------------------
extern "C" void kernel_launch(void* const* d_in, const int* in_sizes, int n_in,
                              void* d_out, int out_size) {
    (void)in_sizes; (void)n_in; (void)out_size;
    const float* x      = (const float*)d_in[0];
    const float* time_w = (const float*)d_in[1];
    const float* alpha  = (const float*)d_in[2];
    const float* beta   = (const float*)d_in[3];
    const float* gamma  = (const float*)d_in[4];
    const float* Wk = (const float*)d_in[5];
    const float* bk = (const float*)d_in[6];
    const float* Wv = (const float*)d_in[7];
    const float* bv = (const float*)d_in[8];
    const float* Wr = (const float*)d_in[9];
    const float* br = (const float*)d_in[10];
    const float* Wo = (const float*)d_in[11];
    const float* bo = (const float*)d_in[12];
    float* out = (float*)d_out;

    float *kvr;
    uint32_t *Ah, *Al;
    cudaGetSymbolAddress((void**)&kvr, g_kvr);
    cudaGetSymbolAddress((void**)&Ah,  g_Ah);
    cudaGetSymbolAddress((void**)&Al,  g_Al);

    size_t smem = 9 * WS * 4;   // 90KB (3 regions x 3 stages)
    static int attr_set = 0;
    if (!attr_set) {
        cudaFuncSetAttribute(gemm_f16x2_k32<0>,
                             cudaFuncAttributeMaxDynamicSharedMemorySize, (int)smem);
        cudaFuncSetAttribute(gemm_f16x2_k32<1>,
                             cudaFuncAttributeMaxDynamicSharedMemorySize, (int)smem);
        attr_set = 1;
    }

    split_w_all_kernel<<<4 * NC * KH / 256, 256>>>(Wk, Wv, Wr, Wo);
    build_W_kernel<<<NH * NT * KH / 256, 256>>>(time_w, alpha);
    build_xs_split_kernel<<<NM * KH / 256, 256>>>(x);

    gemm_f16x2_k32<0><<<dim3(NM / 128, 24), 256, smem>>>(Ah, Al, kvr, bk, bv, br, nullptr);

    cumsumA_kernel<<<dim3(NC / 256, NB, NSEG), 256>>>();
    segscan_kernel<<<dim3(NC / 256, NB), 256>>>();

    kvt_split_kernel<<<dim3(NT / 64, NB * NH), 256>>>();
    wkv_mma_kernel<<<dim3(NT / 64, NB * NH), 256>>>(beta);

    rwkv_split_kernel<<<NM * KH / 256, 256>>>();

    gemm_f16x2_k32<1><<<dim3(NM / 128, 8), 256, smem>>>(Ah, Al, out, bo, nullptr, nullptr, gamma);
}

// round 12
// speedup vs baseline: 1.5979x; 1.2867x over previous
#include <cuda_runtime.h>
#include <cuda_fp16.h>
#include <math.h>
#include <stdint.h>

#define NB 8
#define NT 1024
#define NC 1024
#define NH 16
#define NM (NB*NT)
#define KH 512            // K/2 (fp16 pairs packed along K)
#define NSEG 8
#define TSEG (NT/NSEG)

// ---------------- scratch (static device globals, no allocation) -------------
__device__ float    g_kvr [3*NM*NC];      // k, v, r
__device__ float    g_sumk[NM*NC];        // per-segment local cumsum
__device__ float    g_segtot[NB*NSEG*NC];
__device__ float    g_segoff[NB*NSEG*NC];
__device__ float    g_wkv [NM*NC];
__device__ uint32_t g_Ah  [NM*KH];        // packed f16x2 of current A operand
__device__ uint32_t g_Wh  [4*NC*KH];      // Wk,Wv,Wr,Wo rounded to fp16 (B operand)
__device__ uint32_t g_WWh [NH*NT*KH];     // decay matrix W[h][t][u] fp16 (A of wkv)
__device__ uint32_t g_kvTh[NB*NH*64*KH];  // kv^T [bh][c][u-pairs] rounded fp16

// ---------------- helpers -----------------------------------------------------
__device__ __forceinline__ uint32_t pack2h(float a, float b) {
    __half ha = __float2half_rn(a), hb = __float2half_rn(b);
    return (uint32_t)__half_as_ushort(ha) | ((uint32_t)__half_as_ushort(hb) << 16);
}

__device__ __forceinline__ void mma_f16(float* c, const uint32_t* a,
                                        uint32_t b0, uint32_t b1) {
    asm volatile(
        "mma.sync.aligned.m16n8k16.row.col.f32.f16.f16.f32 "
        "{%0,%1,%2,%3},{%4,%5,%6,%7},{%8,%9},{%0,%1,%2,%3};"
        : "+f"(c[0]), "+f"(c[1]), "+f"(c[2]), "+f"(c[3])
        : "r"(a[0]), "r"(a[1]), "r"(a[2]), "r"(a[3]), "r"(b0), "r"(b1));
}

__device__ __forceinline__ void ldm_x4(uint32_t* r, uint32_t addr) {
    asm volatile("ldmatrix.sync.aligned.m8n8.x4.shared.b16 {%0,%1,%2,%3}, [%4];"
                 : "=r"(r[0]), "=r"(r[1]), "=r"(r[2]), "=r"(r[3]) : "r"(addr));
}

__device__ __forceinline__ void cpa16(uint32_t d, const void* s) {
    asm volatile("cp.async.cg.shared.global [%0], [%1], 16;" :: "r"(d), "l"(s));
}
#define CP_COMMIT() asm volatile("cp.async.commit_group;")
#define CP_WAIT1()  asm volatile("cp.async.wait_group 1;")
#define CP_WAIT0()  asm volatile("cp.async.wait_group 0;")

// ---------------- weight round: all 4 weights -> fp16 in one launch -----------
__global__ void split_w_all_kernel(const float* __restrict__ W0,
                                   const float* __restrict__ W1,
                                   const float* __restrict__ W2,
                                   const float* __restrict__ W3) {
    int i = blockIdx.x * 256 + threadIdx.x;       // over 4*NC*KH
    int w = i >> 19;                              // NC*KH = 512K
    int j = i & (NC * KH - 1);
    const float* W = (w == 0) ? W0 : (w == 1) ? W1 : (w == 2) ? W2 : W3;
    float2 v = ((const float2*)W)[j];
    g_Wh[i] = pack2h(v.x, v.y);
}

// ---------------- decay matrix precompute (fp16, causal tiles only) -----------
__global__ void build_W_kernel(const float* __restrict__ tw,
                               const float* __restrict__ alpha) {
    int i = blockIdx.x * 256 + threadIdx.x;       // over NH*NT*KH
    int u = (i & (KH - 1)) * 2;
    int t = (i >> 9) & (NT - 1);
    if ((u >> 6) > (t >> 6)) return;              // never read by wkv
    int h = i >> 19;
    float w0 = 0.f, w1 = 0.f;
    if (u <= t)     w0 = tw[h * NT + 1023 - t + u]     * alpha[h * NT + u];
    if (u + 1 <= t) w1 = tw[h * NT + 1023 - t + u + 1] * alpha[h * NT + u + 1];
    g_WWh[i] = pack2h(w0, w1);
}

// ---------------- time-shift + fp16 round --------------------------------------
__global__ void build_xs_split_kernel(const float* __restrict__ x) {
    int i = blockIdx.x * 256 + threadIdx.x;       // over NM*KH
    int kk2 = i & (KH - 1);
    int row = i >> 9;
    int t = row & (NT - 1);
    int c = kk2 * 2;
    float a = 0.f, b = 0.f;
    if (c < NC / 2) {
        if (t != 0) {
            float2 v = *(const float2*)(x + (size_t)(row - 1) * NC + c);
            a = v.x; b = v.y;
        }
    } else {
        float2 v = *(const float2*)(x + (size_t)row * NC + c);
        a = v.x; b = v.y;
    }
    g_Ah[i] = pack2h(a, b);
}

// ---------------- cumsum phase A: per-segment local scans ---------------------
__global__ void cumsumA_kernel() {
    int c = blockIdx.x * 256 + threadIdx.x;
    int b = blockIdx.y, s = blockIdx.z;
    const float* src = g_kvr  + ((size_t)(b * NT + s * TSEG)) * NC + c;
    float*       dst = g_sumk + ((size_t)(b * NT + s * TSEG)) * NC + c;
    float acc = 0.f;
    for (int t0 = 0; t0 < TSEG; t0 += 16) {
        float buf[16];
#pragma unroll
        for (int j = 0; j < 16; j++) buf[j] = src[(size_t)(t0 + j) * NC];
#pragma unroll
        for (int j = 0; j < 16; j++) { acc += buf[j]; dst[(size_t)(t0 + j) * NC] = acc; }
    }
    g_segtot[(b * NSEG + s) * NC + c] = acc;
}

// ---------------- cumsum phase B: exclusive scan of segment totals ------------
__global__ void segscan_kernel() {
    int c = blockIdx.x * 256 + threadIdx.x;
    int b = blockIdx.y;
    float s = 0.f;
#pragma unroll
    for (int seg = 0; seg < NSEG; seg++) {
        g_segoff[(b * NSEG + seg) * NC + c] = s;
        s += g_segtot[(b * NSEG + seg) * NC + c];
    }
}

// ---------------- rwkv = sigmoid(r)*wkv/(local+offset), fp16 round ------------
__global__ void rwkv_split_kernel() {
    int i = blockIdx.x * 256 + threadIdx.x;       // over NM*KH
    int j = i * 2;
    int row = i >> 9;
    int t = row & (NT - 1);
    int b = row >> 10;
    int c = (i & (KH - 1)) * 2;
    int so = (b * NSEG + (t >> 7)) * NC + c;
    const float* rr = g_kvr + 2 * (size_t)NM * NC;
    float r0 = rr[j], r1 = rr[j + 1];
    float s0 = g_sumk[j]     + g_segoff[so];
    float s1 = g_sumk[j + 1] + g_segoff[so + 1];
    float a = (1.f / (1.f + expf(-r0))) * g_wkv[j]     / s0;
    float bq = (1.f / (1.f + expf(-r1))) * g_wkv[j + 1] / s1;
    g_Ah[i] = pack2h(a, bq);
}

// ---------------- kv^T: round to fp16 (B operand of wkv) ----------------------
__global__ void kvt_split_kernel() {
    __shared__ float skv[64][65];
    int ut = blockIdx.x;
    int bh = blockIdx.y;
    int b = bh >> 4, h = bh & 15;
    int tid = threadIdx.x;
    int u0 = ut * 64;
    const float* kb = g_kvr + ((size_t)(b * NT + u0)) * NC + h * 64;
    const float* vb = g_kvr + (size_t)NM * NC + ((size_t)(b * NT + u0)) * NC + h * 64;
#pragma unroll
    for (int rr = 0; rr < 16; rr++) {
        int i = tid + rr * 256;
        int uu = i >> 6, c = i & 63;
        skv[uu][c] = kb[(size_t)uu * NC + c] * vb[(size_t)uu * NC + c];
    }
    __syncthreads();
    uint32_t* oh = g_kvTh + (size_t)bh * 64 * KH + ut * 32;
#pragma unroll
    for (int rr = 0; rr < 8; rr++) {
        int j = tid + rr * 256;
        int c = j >> 5, g = j & 31;
        oh[(size_t)c * KH + g] = pack2h(skv[g * 2][c], skv[g * 2 + 1][c]);
    }
}

// ---------------- wkv via tensor cores (fp16, causal, 3-stage pipe) ------------
// Regions (3 stages each): [WWh | Kh]
#define WR 20
#define WST (64*WR)

__global__ void __launch_bounds__(256) wkv_mma_kernel(const float* __restrict__ beta) {
    __shared__ uint32_t smw[6 * WST];       // 30KB
    int tt = blockIdx.x, bh = blockIdx.y;
    int b = bh >> 4, h = bh & 15;
    int t0 = tt * 64;
    int tid = threadIdx.x;
    int lrow = tid >> 2, lq = (tid & 3) * 4;

    const uint32_t* pWh = g_WWh + ((size_t)h * NT + t0 + lrow) * KH + lq;
    const uint32_t* pKh = g_kvTh + ((size_t)bh * 64 + lrow) * KH + lq;
    uint32_t smw_b = (uint32_t)__cvta_generic_to_shared(smw);
    uint32_t sb = smw_b + (lrow * WR + lq) * 4;

    int lane = tid & 31, warp = tid >> 5;
    int wm = (warp >> 1) * 16, wn = (warp & 1) * 32;
    int r = lane >> 2, cc = lane & 3;

    int a_base = (wm + (lane & 15)) * WR + (lane >> 4) * 4;
    int b_base = (wn + ((lane >> 4) << 3) + (lane & 7)) * WR + ((lane >> 3) & 1) * 4;

    float acc[4][4];
#pragma unroll
    for (int i = 0; i < 4; i++)
#pragma unroll
        for (int j = 0; j < 4; j++) acc[i][j] = 0.f;

    int nut = 2 * (tt + 1);     // >= 2

#pragma unroll
    for (int s = 0; s < 2; s++) {
        uint32_t d = sb + s * WST * 4;
        int o = s * 16;
        cpa16(d,               pWh + o);
        cpa16(d + 3 * WST * 4, pKh + o);
        CP_COMMIT();
    }

    for (int ut = 0; ut < nut; ut++) {
        if (ut + 1 < nut) CP_WAIT1(); else CP_WAIT0();
        __syncthreads();
        if (ut + 2 < nut) {
            int slot = (ut + 2) % 3;
            uint32_t d = sb + slot * WST * 4;
            int o = (ut + 2) * 16;
            cpa16(d,               pWh + o);
            cpa16(d + 3 * WST * 4, pKh + o);
            CP_COMMIT();
        }

        uint32_t stoff = (ut % 3) * WST;
#pragma unroll
        for (int ks = 0; ks < 2; ks++) {
            uint32_t ah[4];
            uint32_t ai = smw_b + (stoff + a_base + ks * 8) * 4;
            ldm_x4(ah, ai);

            uint32_t bhf[2][4];
#pragma unroll
            for (int jp = 0; jp < 2; jp++) {
                uint32_t bi = smw_b + (stoff + b_base + jp * 16 * WR + ks * 8) * 4;
                ldm_x4(bhf[jp], bi + 3 * WST * 4);
            }
#pragma unroll
            for (int jp = 0; jp < 2; jp++)
#pragma unroll
                for (int hf = 0; hf < 2; hf++)
                    mma_f16(acc[jp * 2 + hf], ah, bhf[jp][hf * 2], bhf[jp][hf * 2 + 1]);
        }
    }

    int tlo = t0 + wm + r, thi = tlo + 8;
    float be_lo = beta[h * NT + tlo], be_hi = beta[h * NT + thi];
    float* orow_lo = g_wkv + ((size_t)(b * NT + tlo)) * NC + h * 64;
    float* orow_hi = g_wkv + ((size_t)(b * NT + thi)) * NC + h * 64;
#pragma unroll
    for (int nj = 0; nj < 4; nj++) {
        int col = wn + nj * 8 + cc * 2;
        float2 o1 = {acc[nj][0] * be_lo, acc[nj][1] * be_lo};
        float2 o2 = {acc[nj][2] * be_hi, acc[nj][3] * be_hi};
        *(float2*)&orow_lo[col] = o1;
        *(float2*)&orow_hi[col] = o2;
    }
}

// ---------------- fp16 GEMM, K-tile 32, 3-stage pipe, single term -------------
// MODE 0: grid (64,24); sel=by>>3 picks {Wk,Wv,Wr}; exp epilogue for sel==0.
// MODE 1: grid (64,8); weight slab 3 (Wo); bias bo; *gamma[t] epilogue.
#define RS 20                  // row stride in u32 (16 data + 4 pad)
#define WS (128*RS)            // u32 per region per stage

template<int MODE>
__global__ void __launch_bounds__(256, 2) gemm_f16_k32(
    const uint32_t* __restrict__ Ah,
    float* __restrict__ Cout,
    const float* __restrict__ b0p, const float* __restrict__ b1p,
    const float* __restrict__ b2p, const float* __restrict__ gamma)
{
    extern __shared__ uint32_t sm[];   // [Ah:3][Bh:3] stages
    int tid = threadIdx.x;
    int m0 = blockIdx.x * 128;
    int sel, n0;
    const float* bias;
    float* C;
    if (MODE == 0) {
        sel = blockIdx.y >> 3;
        n0 = (blockIdx.y & 7) * 128;
        bias = (sel == 0) ? b0p : (sel == 1) ? b1p : b2p;
        C = Cout + (size_t)sel * NM * NC;
    } else {
        sel = 3;
        n0 = blockIdx.y * 128;
        bias = b0p;
        C = Cout;
    }
    const uint32_t* Bh = g_Wh + (size_t)sel * NC * KH;

    int lrow = tid >> 1;
    int lg = (tid & 1) * 8;
    const uint32_t* pAh = Ah + (size_t)(m0 + lrow) * KH + lg;
    const uint32_t* pBh = Bh + (size_t)(n0 + lrow) * KH + lg;
    uint32_t smem_b = (uint32_t)__cvta_generic_to_shared(sm);
    uint32_t sbase = smem_b + (lrow * RS + lg) * 4;

    int lane = tid & 31, warp = tid >> 5;
    int wm = (warp >> 1) * 32, wn = (warp & 1) * 64;
    int r = lane >> 2, cc = lane & 3;

    int a_base = (wm + (lane & 15)) * RS + (lane >> 4) * 4;
    int b_base = (wn + ((lane >> 4) << 3) + (lane & 7)) * RS + ((lane >> 3) & 1) * 4;

    float acc[2][8][4];
#pragma unroll
    for (int a = 0; a < 2; a++)
#pragma unroll
        for (int b = 0; b < 8; b++)
#pragma unroll
            for (int q = 0; q < 4; q++) acc[a][b][q] = 0.f;

    // prologue: stages 0, 1
#pragma unroll
    for (int s = 0; s < 2; s++) {
        uint32_t d = sbase + s * WS * 4;
        int o = s * 16;
        cpa16(d,          pAh + o);  cpa16(d + 16,          pAh + o + 4);
        cpa16(d + 3*WS*4, pBh + o);  cpa16(d + 3*WS*4 + 16, pBh + o + 4);
        CP_COMMIT();
    }

    for (int kt = 0; kt < 32; kt++) {
        if (kt + 1 < 32) CP_WAIT1(); else CP_WAIT0();
        __syncthreads();
        if (kt + 2 < 32) {
            int slot = (kt + 2) % 3;
            uint32_t d = sbase + slot * WS * 4;
            int o = (kt + 2) * 16;
            cpa16(d,          pAh + o);  cpa16(d + 16,          pAh + o + 4);
            cpa16(d + 3*WS*4, pBh + o);  cpa16(d + 3*WS*4 + 16, pBh + o + 4);
            CP_COMMIT();
        }

        uint32_t st = (kt % 3) * WS;
#pragma unroll
        for (int ks = 0; ks < 2; ks++) {
            uint32_t ah[2][4];
#pragma unroll
            for (int mi = 0; mi < 2; mi++) {
                uint32_t ai = smem_b + (st + a_base + mi * 16 * RS + ks * 8) * 4;
                ldm_x4(ah[mi], ai);
            }
#pragma unroll
            for (int jp = 0; jp < 4; jp++) {
                uint32_t bb[4];
                uint32_t bi = smem_b + (st + b_base + jp * 16 * RS + ks * 8) * 4;
                ldm_x4(bb, bi + 3 * WS * 4);
#pragma unroll
                for (int hf = 0; hf < 2; hf++)
#pragma unroll
                    for (int mi = 0; mi < 2; mi++)
                        mma_f16(acc[mi][jp * 2 + hf], ah[mi], bb[hf * 2], bb[hf * 2 + 1]);
            }
        }
    }

#pragma unroll
    for (int mi = 0; mi < 2; mi++) {
        int mlo = m0 + wm + mi * 16 + r;
        int mhi = mlo + 8;
        float glo = 1.f, ghi = 1.f;
        if (MODE == 1) { glo = gamma[mlo & (NT - 1)]; ghi = gamma[mhi & (NT - 1)]; }
#pragma unroll
        for (int nj = 0; nj < 8; nj++) {
            int col = n0 + wn + nj * 8 + cc * 2;
            float b0 = bias[col], b1 = bias[col + 1];
            float v0 = acc[mi][nj][0] + b0, v1 = acc[mi][nj][1] + b1;
            float v2 = acc[mi][nj][2] + b0, v3 = acc[mi][nj][3] + b1;
            if (MODE == 0) {
                if (sel == 0) {
                    v0 = expf(fminf(fmaxf(v0, -60.f), 30.f));
                    v1 = expf(fminf(fmaxf(v1, -60.f), 30.f));
                    v2 = expf(fminf(fmaxf(v2, -60.f), 30.f));
                    v3 = expf(fminf(fmaxf(v3, -60.f), 30.f));
                }
            } else {
                v0 *= glo; v1 *= glo; v2 *= ghi; v3 *= ghi;
            }
            float2 o01 = {v0, v1}, o23 = {v2, v3};
            *(float2*)&C[(size_t)mlo * NC + col] = o01;
            *(float2*)&C[(size_t)mhi * NC + col] = o23;
        }
    }
}

// ---------------- host launch -------------------------------------------------
extern "C" void kernel_launch(void* const* d_in, const int* in_sizes, int n_in,
                              void* d_out, int out_size) {
    (void)in_sizes; (void)n_in; (void)out_size;
    const float* x      = (const float*)d_in[0];
    const float* time_w = (const float*)d_in[1];
    const float* alpha  = (const float*)d_in[2];
    const float* beta   = (const float*)d_in[3];
    const float* gamma  = (const float*)d_in[4];
    const float* Wk = (const float*)d_in[5];
    const float* bk = (const float*)d_in[6];
    const float* Wv = (const float*)d_in[7];
    const float* bv = (const float*)d_in[8];
    const float* Wr = (const float*)d_in[9];
    const float* br = (const float*)d_in[10];
    const float* Wo = (const float*)d_in[11];
    const float* bo = (const float*)d_in[12];
    float* out = (float*)d_out;

    float *kvr;
    uint32_t *Ah;
    cudaGetSymbolAddress((void**)&kvr, g_kvr);
    cudaGetSymbolAddress((void**)&Ah,  g_Ah);

    size_t smem = 6 * WS * 4;   // 60KB (2 regions x 3 stages)
    static int attr_set = 0;
    if (!attr_set) {
        cudaFuncSetAttribute(gemm_f16_k32<0>,
                             cudaFuncAttributeMaxDynamicSharedMemorySize, (int)smem);
        cudaFuncSetAttribute(gemm_f16_k32<1>,
                             cudaFuncAttributeMaxDynamicSharedMemorySize, (int)smem);
        attr_set = 1;
    }

    split_w_all_kernel<<<4 * NC * KH / 256, 256>>>(Wk, Wv, Wr, Wo);
    build_W_kernel<<<NH * NT * KH / 256, 256>>>(time_w, alpha);
    build_xs_split_kernel<<<NM * KH / 256, 256>>>(x);

    gemm_f16_k32<0><<<dim3(NM / 128, 24), 256, smem>>>(Ah, kvr, bk, bv, br, nullptr);

    cumsumA_kernel<<<dim3(NC / 256, NB, NSEG), 256>>>();
    segscan_kernel<<<dim3(NC / 256, NB), 256>>>();

    kvt_split_kernel<<<dim3(NT / 64, NB * NH), 256>>>();
    wkv_mma_kernel<<<dim3(NT / 64, NB * NH), 256>>>(beta);

    rwkv_split_kernel<<<NM * KH / 256, 256>>>();

    gemm_f16_k32<1><<<dim3(NM / 128, 8), 256, smem>>>(Ah, out, bo, nullptr, nullptr, gamma);
}

// round 13
// speedup vs baseline: 1.6583x; 1.0378x over previous
#include <cuda_runtime.h>
#include <cuda_fp16.h>
#include <math.h>
#include <stdint.h>

#define NB 8
#define NT 1024
#define NC 1024
#define NH 16
#define NM (NB*NT)
#define KH 512            // K/2 (fp16 pairs packed along K)
#define NSEG 8
#define TSEG (NT/NSEG)

// ---------------- scratch (static device globals, no allocation) -------------
__device__ float    g_kvr [3*NM*NC];      // k, v, r
__device__ float    g_sumk[NM*NC];        // per-segment local cumsum
__device__ float    g_segtot[NB*NSEG*NC];
__device__ float    g_segoff[NB*NSEG*NC];
__device__ float    g_wkv [NM*NC];
__device__ uint32_t g_Ah  [NM*KH];        // packed f16x2 of current A operand
__device__ uint32_t g_Wh  [4*NC*KH];      // Wk,Wv,Wr,Wo rounded to fp16 (B operand)
__device__ uint32_t g_WWh [NH*NT*KH];     // decay matrix W[h][t][u] fp16 (A of wkv)
__device__ uint32_t g_kvTh[NB*NH*64*KH];  // kv^T [bh][c][u-pairs] rounded fp16

// ---------------- helpers -----------------------------------------------------
__device__ __forceinline__ uint32_t pack2h(float a, float b) {
    __half ha = __float2half_rn(a), hb = __float2half_rn(b);
    return (uint32_t)__half_as_ushort(ha) | ((uint32_t)__half_as_ushort(hb) << 16);
}

__device__ __forceinline__ void mma_f16(float* c, const uint32_t* a,
                                        uint32_t b0, uint32_t b1) {
    asm volatile(
        "mma.sync.aligned.m16n8k16.row.col.f32.f16.f16.f32 "
        "{%0,%1,%2,%3},{%4,%5,%6,%7},{%8,%9},{%0,%1,%2,%3};"
        : "+f"(c[0]), "+f"(c[1]), "+f"(c[2]), "+f"(c[3])
        : "r"(a[0]), "r"(a[1]), "r"(a[2]), "r"(a[3]), "r"(b0), "r"(b1));
}

__device__ __forceinline__ void ldm_x4(uint32_t* r, uint32_t addr) {
    asm volatile("ldmatrix.sync.aligned.m8n8.x4.shared.b16 {%0,%1,%2,%3}, [%4];"
                 : "=r"(r[0]), "=r"(r[1]), "=r"(r[2]), "=r"(r[3]) : "r"(addr));
}

__device__ __forceinline__ void cpa16(uint32_t d, const void* s) {
    asm volatile("cp.async.cg.shared.global [%0], [%1], 16;" :: "r"(d), "l"(s));
}
#define CP_COMMIT() asm volatile("cp.async.commit_group;")
#define CP_WAIT1()  asm volatile("cp.async.wait_group 1;")
#define CP_WAIT0()  asm volatile("cp.async.wait_group 0;")

// ---------------- fused prep: weights round + decay matrix + time-shift -------
#define PREP_B0 (4*NC*KH/256)             // 8192 blocks: weight rounding
#define PREP_B1 (NH*NT*KH/256)            // 32768 blocks: decay matrix
#define PREP_B2 (NM*KH/256)               // 16384 blocks: time-shift xs

__global__ void prep_kernel(const float* __restrict__ W0, const float* __restrict__ W1,
                            const float* __restrict__ W2, const float* __restrict__ W3,
                            const float* __restrict__ tw, const float* __restrict__ alpha,
                            const float* __restrict__ x) {
    int blk = blockIdx.x;
    if (blk < PREP_B0) {
        int i = blk * 256 + threadIdx.x;
        int w = i >> 19;
        int j = i & (NC * KH - 1);
        const float* W = (w == 0) ? W0 : (w == 1) ? W1 : (w == 2) ? W2 : W3;
        float2 v = ((const float2*)W)[j];
        g_Wh[i] = pack2h(v.x, v.y);
    } else if (blk < PREP_B0 + PREP_B1) {
        int i = (blk - PREP_B0) * 256 + threadIdx.x;
        int u = (i & (KH - 1)) * 2;
        int t = (i >> 9) & (NT - 1);
        if ((u >> 6) > (t >> 6)) return;
        int h = i >> 19;
        float w0 = 0.f, w1 = 0.f;
        if (u <= t)     w0 = tw[h * NT + 1023 - t + u]     * alpha[h * NT + u];
        if (u + 1 <= t) w1 = tw[h * NT + 1023 - t + u + 1] * alpha[h * NT + u + 1];
        g_WWh[i] = pack2h(w0, w1);
    } else {
        int i = (blk - PREP_B0 - PREP_B1) * 256 + threadIdx.x;
        int kk2 = i & (KH - 1);
        int row = i >> 9;
        int t = row & (NT - 1);
        int c = kk2 * 2;
        float a = 0.f, b = 0.f;
        if (c < NC / 2) {
            if (t != 0) {
                float2 v = *(const float2*)(x + (size_t)(row - 1) * NC + c);
                a = v.x; b = v.y;
            }
        } else {
            float2 v = *(const float2*)(x + (size_t)row * NC + c);
            a = v.x; b = v.y;
        }
        g_Ah[i] = pack2h(a, b);
    }
}

// ---------------- cumsum phase A: per-segment local scans ---------------------
__global__ void cumsumA_kernel() {
    int c = blockIdx.x * 256 + threadIdx.x;
    int b = blockIdx.y, s = blockIdx.z;
    const float* src = g_kvr  + ((size_t)(b * NT + s * TSEG)) * NC + c;
    float*       dst = g_sumk + ((size_t)(b * NT + s * TSEG)) * NC + c;
    float acc = 0.f;
    for (int t0 = 0; t0 < TSEG; t0 += 16) {
        float buf[16];
#pragma unroll
        for (int j = 0; j < 16; j++) buf[j] = src[(size_t)(t0 + j) * NC];
#pragma unroll
        for (int j = 0; j < 16; j++) { acc += buf[j]; dst[(size_t)(t0 + j) * NC] = acc; }
    }
    g_segtot[(b * NSEG + s) * NC + c] = acc;
}

// ---------------- cumsum phase B: exclusive scan of segment totals ------------
__global__ void segscan_kernel() {
    int c = blockIdx.x * 256 + threadIdx.x;
    int b = blockIdx.y;
    float s = 0.f;
#pragma unroll
    for (int seg = 0; seg < NSEG; seg++) {
        g_segoff[(b * NSEG + seg) * NC + c] = s;
        s += g_segtot[(b * NSEG + seg) * NC + c];
    }
}

// ---------------- rwkv = sigmoid(r)*wkv/(local+offset), fp16 round ------------
__global__ void rwkv_split_kernel() {
    int i = blockIdx.x * 256 + threadIdx.x;       // over NM*KH
    int j = i * 2;
    int row = i >> 9;
    int t = row & (NT - 1);
    int b = row >> 10;
    int c = (i & (KH - 1)) * 2;
    int so = (b * NSEG + (t >> 7)) * NC + c;
    const float* rr = g_kvr + 2 * (size_t)NM * NC;
    float r0 = rr[j], r1 = rr[j + 1];
    float s0 = g_sumk[j]     + g_segoff[so];
    float s1 = g_sumk[j + 1] + g_segoff[so + 1];
    float a = (1.f / (1.f + expf(-r0))) * g_wkv[j]     / s0;
    float bq = (1.f / (1.f + expf(-r1))) * g_wkv[j + 1] / s1;
    g_Ah[i] = pack2h(a, bq);
}

// ---------------- kv^T: round to fp16 (B operand of wkv) ----------------------
__global__ void kvt_split_kernel() {
    __shared__ float skv[64][65];
    int ut = blockIdx.x;
    int bh = blockIdx.y;
    int b = bh >> 4, h = bh & 15;
    int tid = threadIdx.x;
    int u0 = ut * 64;
    const float* kb = g_kvr + ((size_t)(b * NT + u0)) * NC + h * 64;
    const float* vb = g_kvr + (size_t)NM * NC + ((size_t)(b * NT + u0)) * NC + h * 64;
#pragma unroll
    for (int rr = 0; rr < 16; rr++) {
        int i = tid + rr * 256;
        int uu = i >> 6, c = i & 63;
        skv[uu][c] = kb[(size_t)uu * NC + c] * vb[(size_t)uu * NC + c];
    }
    __syncthreads();
    uint32_t* oh = g_kvTh + (size_t)bh * 64 * KH + ut * 32;
#pragma unroll
    for (int rr = 0; rr < 8; rr++) {
        int j = tid + rr * 256;
        int c = j >> 5, g = j & 31;
        oh[(size_t)c * KH + g] = pack2h(skv[g * 2][c], skv[g * 2 + 1][c]);
    }
}

// ---------------- wkv via tensor cores (fp16, causal, 3-stage pipe) ------------
// Regions (3 stages each): [WWh | Kh]
#define WR 20
#define WST (64*WR)

__global__ void __launch_bounds__(256) wkv_mma_kernel(const float* __restrict__ beta) {
    __shared__ uint32_t smw[6 * WST];       // 30KB
    int tt = blockIdx.x, bh = blockIdx.y;
    int b = bh >> 4, h = bh & 15;
    int t0 = tt * 64;
    int tid = threadIdx.x;
    int lrow = tid >> 2, lq = (tid & 3) * 4;

    const uint32_t* pWh = g_WWh + ((size_t)h * NT + t0 + lrow) * KH + lq;
    const uint32_t* pKh = g_kvTh + ((size_t)bh * 64 + lrow) * KH + lq;
    uint32_t smw_b = (uint32_t)__cvta_generic_to_shared(smw);
    uint32_t sb = smw_b + (lrow * WR + lq) * 4;

    int lane = tid & 31, warp = tid >> 5;
    int wm = (warp >> 1) * 16, wn = (warp & 1) * 32;
    int r = lane >> 2, cc = lane & 3;

    int a_base = (wm + (lane & 15)) * WR + (lane >> 4) * 4;
    int b_base = (wn + ((lane >> 4) << 3) + (lane & 7)) * WR + ((lane >> 3) & 1) * 4;

    float acc[4][4];
#pragma unroll
    for (int i = 0; i < 4; i++)
#pragma unroll
        for (int j = 0; j < 4; j++) acc[i][j] = 0.f;

    int nut = 2 * (tt + 1);     // >= 2

#pragma unroll
    for (int s = 0; s < 2; s++) {
        uint32_t d = sb + s * WST * 4;
        int o = s * 16;
        cpa16(d,               pWh + o);
        cpa16(d + 3 * WST * 4, pKh + o);
        CP_COMMIT();
    }

    for (int ut = 0; ut < nut; ut++) {
        if (ut + 1 < nut) CP_WAIT1(); else CP_WAIT0();
        __syncthreads();
        if (ut + 2 < nut) {
            int slot = (ut + 2) % 3;
            uint32_t d = sb + slot * WST * 4;
            int o = (ut + 2) * 16;
            cpa16(d,               pWh + o);
            cpa16(d + 3 * WST * 4, pKh + o);
            CP_COMMIT();
        }

        uint32_t stoff = (ut % 3) * WST;
#pragma unroll
        for (int ks = 0; ks < 2; ks++) {
            uint32_t ah[4];
            uint32_t ai = smw_b + (stoff + a_base + ks * 8) * 4;
            ldm_x4(ah, ai);

            uint32_t bhf[2][4];
#pragma unroll
            for (int jp = 0; jp < 2; jp++) {
                uint32_t bi = smw_b + (stoff + b_base + jp * 16 * WR + ks * 8) * 4;
                ldm_x4(bhf[jp], bi + 3 * WST * 4);
            }
#pragma unroll
            for (int jp = 0; jp < 2; jp++)
#pragma unroll
                for (int hf = 0; hf < 2; hf++)
                    mma_f16(acc[jp * 2 + hf], ah, bhf[jp][hf * 2], bhf[jp][hf * 2 + 1]);
        }
    }

    int tlo = t0 + wm + r, thi = tlo + 8;
    float be_lo = beta[h * NT + tlo], be_hi = beta[h * NT + thi];
    float* orow_lo = g_wkv + ((size_t)(b * NT + tlo)) * NC + h * 64;
    float* orow_hi = g_wkv + ((size_t)(b * NT + thi)) * NC + h * 64;
#pragma unroll
    for (int nj = 0; nj < 4; nj++) {
        int col = wn + nj * 8 + cc * 2;
        float2 o1 = {acc[nj][0] * be_lo, acc[nj][1] * be_lo};
        float2 o2 = {acc[nj][2] * be_hi, acc[nj][3] * be_hi};
        *(float2*)&orow_lo[col] = o1;
        *(float2*)&orow_hi[col] = o2;
    }
}

// ---------------- fp16 GEMM, 128x64 block, 32x32 warp tile, 3 CTAs/SM ---------
// MODE 0: grid (64,48); sel=by>>4 picks {Wk,Wv,Wr}; n0=(by&15)*64; exp for sel==0.
// MODE 1: grid (64,16); weight slab 3 (Wo); bias bo; *gamma[t] epilogue.
#define RS 20                   // row stride in u32 (16 data + 4 pad)
#define AS (128*RS)             // u32 per A region per stage
#define BS (64*RS)              // u32 per B region per stage
#define STG (AS+BS)             // u32 per stage

template<int MODE>
__global__ void __launch_bounds__(256, 3) gemm_f16_n64(
    const uint32_t* __restrict__ Ah,
    float* __restrict__ Cout,
    const float* __restrict__ b0p, const float* __restrict__ b1p,
    const float* __restrict__ b2p, const float* __restrict__ gamma)
{
    extern __shared__ uint32_t sm[];   // 3 stages x [A(128 rows) | B(64 rows)]
    int tid = threadIdx.x;
    int m0 = blockIdx.x * 128;
    int sel, n0;
    const float* bias;
    float* C;
    if (MODE == 0) {
        sel = blockIdx.y >> 4;
        n0 = (blockIdx.y & 15) * 64;
        bias = (sel == 0) ? b0p : (sel == 1) ? b1p : b2p;
        C = Cout + (size_t)sel * NM * NC;
    } else {
        sel = 3;
        n0 = blockIdx.y * 64;
        bias = b0p;
        C = Cout;
    }
    const uint32_t* Bh = g_Wh + (size_t)sel * NC * KH;

    // A loads: 128 rows x 16 u32 -> 2 cpa16/thread. B: 64 rows x 16 u32 -> 1 cpa16.
    int arow = tid >> 1, ag = (tid & 1) * 8;
    int brow = tid >> 2, bg = (tid & 3) * 4;
    const uint32_t* pAh = Ah + (size_t)(m0 + arow) * KH + ag;
    const uint32_t* pBh = Bh + (size_t)(n0 + brow) * KH + bg;
    uint32_t smem_b = (uint32_t)__cvta_generic_to_shared(sm);
    uint32_t sA = smem_b + (arow * RS + ag) * 4;
    uint32_t sB = smem_b + (AS + brow * RS + bg) * 4;

    int lane = tid & 31, warp = tid >> 5;
    int wm = (warp & 3) * 32, wn = (warp >> 2) * 32;
    int r = lane >> 2, cc = lane & 3;

    int a_base = (wm + (lane & 15)) * RS + (lane >> 4) * 4;
    int b_base = AS + (wn + ((lane >> 4) << 3) + (lane & 7)) * RS + ((lane >> 3) & 1) * 4;

    float acc[2][4][4];
#pragma unroll
    for (int a = 0; a < 2; a++)
#pragma unroll
        for (int b = 0; b < 4; b++)
#pragma unroll
            for (int q = 0; q < 4; q++) acc[a][b][q] = 0.f;

    // prologue: stages 0, 1
#pragma unroll
    for (int s = 0; s < 2; s++) {
        int o = s * 16;
        uint32_t dA = sA + s * STG * 4;
        uint32_t dB = sB + s * STG * 4;
        cpa16(dA, pAh + o); cpa16(dA + 16, pAh + o + 4);
        cpa16(dB, pBh + o);
        CP_COMMIT();
    }

    for (int kt = 0; kt < 32; kt++) {
        if (kt + 1 < 32) CP_WAIT1(); else CP_WAIT0();
        __syncthreads();
        if (kt + 2 < 32) {
            int slot = (kt + 2) % 3;
            int o = (kt + 2) * 16;
            uint32_t dA = sA + slot * STG * 4;
            uint32_t dB = sB + slot * STG * 4;
            cpa16(dA, pAh + o); cpa16(dA + 16, pAh + o + 4);
            cpa16(dB, pBh + o);
            CP_COMMIT();
        }

        uint32_t st = (kt % 3) * STG;
#pragma unroll
        for (int ks = 0; ks < 2; ks++) {
            uint32_t ahf[2][4];
#pragma unroll
            for (int mi = 0; mi < 2; mi++) {
                uint32_t ai = smem_b + (st + a_base + mi * 16 * RS + ks * 8) * 4;
                ldm_x4(ahf[mi], ai);
            }
#pragma unroll
            for (int jp = 0; jp < 2; jp++) {
                uint32_t bb[4];
                uint32_t bi = smem_b + (st + b_base + jp * 16 * RS + ks * 8) * 4;
                ldm_x4(bb, bi);
#pragma unroll
                for (int hf = 0; hf < 2; hf++)
#pragma unroll
                    for (int mi = 0; mi < 2; mi++)
                        mma_f16(acc[mi][jp * 2 + hf], ahf[mi], bb[hf * 2], bb[hf * 2 + 1]);
            }
        }
    }

#pragma unroll
    for (int mi = 0; mi < 2; mi++) {
        int mlo = m0 + wm + mi * 16 + r;
        int mhi = mlo + 8;
        float glo = 1.f, ghi = 1.f;
        if (MODE == 1) { glo = gamma[mlo & (NT - 1)]; ghi = gamma[mhi & (NT - 1)]; }
#pragma unroll
        for (int nj = 0; nj < 4; nj++) {
            int col = n0 + wn + nj * 8 + cc * 2;
            float b0 = bias[col], b1 = bias[col + 1];
            float v0 = acc[mi][nj][0] + b0, v1 = acc[mi][nj][1] + b1;
            float v2 = acc[mi][nj][2] + b0, v3 = acc[mi][nj][3] + b1;
            if (MODE == 0) {
                if (sel == 0) {
                    v0 = expf(fminf(fmaxf(v0, -60.f), 30.f));
                    v1 = expf(fminf(fmaxf(v1, -60.f), 30.f));
                    v2 = expf(fminf(fmaxf(v2, -60.f), 30.f));
                    v3 = expf(fminf(fmaxf(v3, -60.f), 30.f));
                }
            } else {
                v0 *= glo; v1 *= glo; v2 *= ghi; v3 *= ghi;
            }
            float2 o01 = {v0, v1}, o23 = {v2, v3};
            *(float2*)&C[(size_t)mlo * NC + col] = o01;
            *(float2*)&C[(size_t)mhi * NC + col] = o23;
        }
    }
}

// ---------------- host launch -------------------------------------------------
extern "C" void kernel_launch(void* const* d_in, const int* in_sizes, int n_in,
                              void* d_out, int out_size) {
    (void)in_sizes; (void)n_in; (void)out_size;
    const float* x      = (const float*)d_in[0];
    const float* time_w = (const float*)d_in[1];
    const float* alpha  = (const float*)d_in[2];
    const float* beta   = (const float*)d_in[3];
    const float* gamma  = (const float*)d_in[4];
    const float* Wk = (const float*)d_in[5];
    const float* bk = (const float*)d_in[6];
    const float* Wv = (const float*)d_in[7];
    const float* bv = (const float*)d_in[8];
    const float* Wr = (const float*)d_in[9];
    const float* br = (const float*)d_in[10];
    const float* Wo = (const float*)d_in[11];
    const float* bo = (const float*)d_in[12];
    float* out = (float*)d_out;

    float *kvr;
    uint32_t *Ah;
    cudaGetSymbolAddress((void**)&kvr, g_kvr);
    cudaGetSymbolAddress((void**)&Ah,  g_Ah);

    size_t smem = 3 * STG * 4;   // 46.08KB (3 stages x [A|B])
    static int attr_set = 0;
    if (!attr_set) {
        cudaFuncSetAttribute(gemm_f16_n64<0>,
                             cudaFuncAttributeMaxDynamicSharedMemorySize, (int)smem);
        cudaFuncSetAttribute(gemm_f16_n64<1>,
                             cudaFuncAttributeMaxDynamicSharedMemorySize, (int)smem);
        attr_set = 1;
    }

    prep_kernel<<<PREP_B0 + PREP_B1 + PREP_B2, 256>>>(Wk, Wv, Wr, Wo, time_w, alpha, x);

    gemm_f16_n64<0><<<dim3(NM / 128, 48), 256, smem>>>(Ah, kvr, bk, bv, br, nullptr);

    cumsumA_kernel<<<dim3(NC / 256, NB, NSEG), 256>>>();
    segscan_kernel<<<dim3(NC / 256, NB), 256>>>();

    kvt_split_kernel<<<dim3(NT / 64, NB * NH), 256>>>();
    wkv_mma_kernel<<<dim3(NT / 64, NB * NH), 256>>>(beta);

    rwkv_split_kernel<<<NM * KH / 256, 256>>>();

    gemm_f16_n64<1><<<dim3(NM / 128, 16), 256, smem>>>(Ah, out, bo, nullptr, nullptr, gamma);
}

// round 14
// speedup vs baseline: 1.6776x; 1.0116x over previous
#include <cuda_runtime.h>
#include <cuda_fp16.h>
#include <math.h>
#include <stdint.h>

#define NB 8
#define NT 1024
#define NC 1024
#define NH 16
#define NM (NB*NT)
#define KH 512            // K/2 (fp16 pairs packed along K)
#define NSEG 8
#define TSEG (NT/NSEG)

// ---------------- scratch (static device globals, no allocation) -------------
__device__ uint32_t g_k16 [NM*KH];        // exp(clip(k)) packed half2
__device__ uint32_t g_v16 [NM*KH];        // v packed half2
__device__ uint32_t g_r16 [NM*KH];        // r packed half2
__device__ float    g_sumk[NM*NC];        // per-segment local cumsum (f32)
__device__ float    g_segtot[NB*NSEG*NC];
__device__ float    g_wkv [NM*NC];
__device__ uint32_t g_Ah  [NM*KH];        // packed f16x2 of current A operand
__device__ uint32_t g_Wh  [4*NC*KH];      // Wk,Wv,Wr,Wo rounded to fp16 (B operand)
__device__ uint32_t g_WWh [NH*NT*KH];     // decay matrix W[h][t][u] fp16 (A of wkv)
__device__ uint32_t g_kvTh[NB*NH*64*KH];  // kv^T [bh][c][u-pairs] rounded fp16

// ---------------- helpers -----------------------------------------------------
__device__ __forceinline__ uint32_t pack2h(float a, float b) {
    __half ha = __float2half_rn(a), hb = __float2half_rn(b);
    return (uint32_t)__half_as_ushort(ha) | ((uint32_t)__half_as_ushort(hb) << 16);
}

__device__ __forceinline__ float2 unpack2h(uint32_t p) {
    __half2 h = *(__half2*)&p;
    return make_float2(__half2float(__low2half(h)), __half2float(__high2half(h)));
}

__device__ __forceinline__ void mma_f16(float* c, const uint32_t* a,
                                        uint32_t b0, uint32_t b1) {
    asm volatile(
        "mma.sync.aligned.m16n8k16.row.col.f32.f16.f16.f32 "
        "{%0,%1,%2,%3},{%4,%5,%6,%7},{%8,%9},{%0,%1,%2,%3};"
        : "+f"(c[0]), "+f"(c[1]), "+f"(c[2]), "+f"(c[3])
        : "r"(a[0]), "r"(a[1]), "r"(a[2]), "r"(a[3]), "r"(b0), "r"(b1));
}

__device__ __forceinline__ void ldm_x4(uint32_t* r, uint32_t addr) {
    asm volatile("ldmatrix.sync.aligned.m8n8.x4.shared.b16 {%0,%1,%2,%3}, [%4];"
                 : "=r"(r[0]), "=r"(r[1]), "=r"(r[2]), "=r"(r[3]) : "r"(addr));
}

__device__ __forceinline__ void cpa16(uint32_t d, const void* s) {
    asm volatile("cp.async.cg.shared.global [%0], [%1], 16;" :: "r"(d), "l"(s));
}
#define CP_COMMIT() asm volatile("cp.async.commit_group;")
#define CP_WAIT1()  asm volatile("cp.async.wait_group 1;")
#define CP_WAIT0()  asm volatile("cp.async.wait_group 0;")

// ---------------- fused prep: weights round + decay matrix + time-shift -------
#define PREP_B0 (4*NC*KH/256)
#define PREP_B1 (NH*NT*KH/256)
#define PREP_B2 (NM*KH/256)

__global__ void prep_kernel(const float* __restrict__ W0, const float* __restrict__ W1,
                            const float* __restrict__ W2, const float* __restrict__ W3,
                            const float* __restrict__ tw, const float* __restrict__ alpha,
                            const float* __restrict__ x) {
    int blk = blockIdx.x;
    if (blk < PREP_B0) {
        int i = blk * 256 + threadIdx.x;
        int w = i >> 19;
        int j = i & (NC * KH - 1);
        const float* W = (w == 0) ? W0 : (w == 1) ? W1 : (w == 2) ? W2 : W3;
        float2 v = ((const float2*)W)[j];
        g_Wh[i] = pack2h(v.x, v.y);
    } else if (blk < PREP_B0 + PREP_B1) {
        int i = (blk - PREP_B0) * 256 + threadIdx.x;
        int u = (i & (KH - 1)) * 2;
        int t = (i >> 9) & (NT - 1);
        if ((u >> 6) > (t >> 6)) return;
        int h = i >> 19;
        float w0 = 0.f, w1 = 0.f;
        if (u <= t)     w0 = tw[h * NT + 1023 - t + u]     * alpha[h * NT + u];
        if (u + 1 <= t) w1 = tw[h * NT + 1023 - t + u + 1] * alpha[h * NT + u + 1];
        g_WWh[i] = pack2h(w0, w1);
    } else {
        int i = (blk - PREP_B0 - PREP_B1) * 256 + threadIdx.x;
        int kk2 = i & (KH - 1);
        int row = i >> 9;
        int t = row & (NT - 1);
        int c = kk2 * 2;
        float a = 0.f, b = 0.f;
        if (c < NC / 2) {
            if (t != 0) {
                float2 v = *(const float2*)(x + (size_t)(row - 1) * NC + c);
                a = v.x; b = v.y;
            }
        } else {
            float2 v = *(const float2*)(x + (size_t)row * NC + c);
            a = v.x; b = v.y;
        }
        g_Ah[i] = pack2h(a, b);
    }
}

// ---------------- cumsum: per-segment local scans (half2 in, f32 out) ---------
__global__ void cumsumA_kernel() {
    int cp = blockIdx.x * 256 + threadIdx.x;      // channel pair 0..511
    int b = blockIdx.y, s = blockIdx.z;
    const uint32_t* src = g_k16 + ((size_t)(b * NT + s * TSEG)) * KH + cp;
    float* dst = g_sumk + ((size_t)(b * NT + s * TSEG)) * NC + cp * 2;
    float a0 = 0.f, a1 = 0.f;
    for (int t0 = 0; t0 < TSEG; t0 += 16) {
        uint32_t buf[16];
#pragma unroll
        for (int j = 0; j < 16; j++) buf[j] = src[(size_t)(t0 + j) * KH];
#pragma unroll
        for (int j = 0; j < 16; j++) {
            float2 kv = unpack2h(buf[j]);
            a0 += kv.x; a1 += kv.y;
            float2 o = {a0, a1};
            *(float2*)&dst[(size_t)(t0 + j) * NC] = o;
        }
    }
    float2 tot = {a0, a1};
    *(float2*)&g_segtot[(b * NSEG + s) * NC + cp * 2] = tot;
}

// ---------------- rwkv = sigmoid(r)*wkv/(local+offset), fp16 round ------------
__global__ void rwkv_split_kernel() {
    int i = blockIdx.x * 256 + threadIdx.x;       // over NM*KH
    int j = i * 2;
    int row = i >> 9;
    int t = row & (NT - 1);
    int b = row >> 10;
    int c = (i & (KH - 1)) * 2;
    // inline segment-offset scan (g_segtot is tiny, L2 resident)
    float so0 = 0.f, so1 = 0.f;
    int nseg = t >> 7;
    for (int sg = 0; sg < nseg; sg++) {
        float2 st = *(const float2*)&g_segtot[(b * NSEG + sg) * NC + c];
        so0 += st.x; so1 += st.y;
    }
    float2 rv = unpack2h(g_r16[i]);
    float s0 = g_sumk[j]     + so0;
    float s1 = g_sumk[j + 1] + so1;
    float a  = (1.f / (1.f + expf(-rv.x))) * g_wkv[j]     / s0;
    float bq = (1.f / (1.f + expf(-rv.y))) * g_wkv[j + 1] / s1;
    g_Ah[i] = pack2h(a, bq);
}

// ---------------- kv^T: product of fp16 k,v -> fp16 (B operand of wkv) --------
__global__ void kvt_split_kernel() {
    __shared__ float skv[64][65];
    int ut = blockIdx.x;
    int bh = blockIdx.y;
    int b = bh >> 4, h = bh & 15;
    int tid = threadIdx.x;
    int u0 = ut * 64;
    const __half* kb = (const __half*)g_k16 + ((size_t)(b * NT + u0)) * NC + h * 64;
    const __half* vb = (const __half*)g_v16 + ((size_t)(b * NT + u0)) * NC + h * 64;
#pragma unroll
    for (int rr = 0; rr < 16; rr++) {
        int i = tid + rr * 256;
        int uu = i >> 6, c = i & 63;
        skv[uu][c] = __half2float(kb[(size_t)uu * NC + c]) *
                     __half2float(vb[(size_t)uu * NC + c]);
    }
    __syncthreads();
    uint32_t* oh = g_kvTh + (size_t)bh * 64 * KH + ut * 32;
#pragma unroll
    for (int rr = 0; rr < 8; rr++) {
        int j = tid + rr * 256;
        int c = j >> 5, g = j & 31;
        oh[(size_t)c * KH + g] = pack2h(skv[g * 2][c], skv[g * 2 + 1][c]);
    }
}

// ---------------- wkv via tensor cores (fp16, causal, 3-stage pipe) ------------
#define WR 20
#define WST (64*WR)

__global__ void __launch_bounds__(256) wkv_mma_kernel(const float* __restrict__ beta) {
    __shared__ uint32_t smw[6 * WST];       // 30KB
    int tt = blockIdx.x, bh = blockIdx.y;
    int b = bh >> 4, h = bh & 15;
    int t0 = tt * 64;
    int tid = threadIdx.x;
    int lrow = tid >> 2, lq = (tid & 3) * 4;

    const uint32_t* pWh = g_WWh + ((size_t)h * NT + t0 + lrow) * KH + lq;
    const uint32_t* pKh = g_kvTh + ((size_t)bh * 64 + lrow) * KH + lq;
    uint32_t smw_b = (uint32_t)__cvta_generic_to_shared(smw);
    uint32_t sb = smw_b + (lrow * WR + lq) * 4;

    int lane = tid & 31, warp = tid >> 5;
    int wm = (warp >> 1) * 16, wn = (warp & 1) * 32;
    int r = lane >> 2, cc = lane & 3;

    int a_base = (wm + (lane & 15)) * WR + (lane >> 4) * 4;
    int b_base = (wn + ((lane >> 4) << 3) + (lane & 7)) * WR + ((lane >> 3) & 1) * 4;

    float acc[4][4];
#pragma unroll
    for (int i = 0; i < 4; i++)
#pragma unroll
        for (int j = 0; j < 4; j++) acc[i][j] = 0.f;

    int nut = 2 * (tt + 1);

#pragma unroll
    for (int s = 0; s < 2; s++) {
        uint32_t d = sb + s * WST * 4;
        int o = s * 16;
        cpa16(d,               pWh + o);
        cpa16(d + 3 * WST * 4, pKh + o);
        CP_COMMIT();
    }

    for (int ut = 0; ut < nut; ut++) {
        if (ut + 1 < nut) CP_WAIT1(); else CP_WAIT0();
        __syncthreads();
        if (ut + 2 < nut) {
            int slot = (ut + 2) % 3;
            uint32_t d = sb + slot * WST * 4;
            int o = (ut + 2) * 16;
            cpa16(d,               pWh + o);
            cpa16(d + 3 * WST * 4, pKh + o);
            CP_COMMIT();
        }

        uint32_t stoff = (ut % 3) * WST;
#pragma unroll
        for (int ks = 0; ks < 2; ks++) {
            uint32_t ah[4];
            uint32_t ai = smw_b + (stoff + a_base + ks * 8) * 4;
            ldm_x4(ah, ai);

            uint32_t bhf[2][4];
#pragma unroll
            for (int jp = 0; jp < 2; jp++) {
                uint32_t bi = smw_b + (stoff + b_base + jp * 16 * WR + ks * 8) * 4;
                ldm_x4(bhf[jp], bi + 3 * WST * 4);
            }
#pragma unroll
            for (int jp = 0; jp < 2; jp++)
#pragma unroll
                for (int hf = 0; hf < 2; hf++)
                    mma_f16(acc[jp * 2 + hf], ah, bhf[jp][hf * 2], bhf[jp][hf * 2 + 1]);
        }
    }

    int tlo = t0 + wm + r, thi = tlo + 8;
    float be_lo = beta[h * NT + tlo], be_hi = beta[h * NT + thi];
    float* orow_lo = g_wkv + ((size_t)(b * NT + tlo)) * NC + h * 64;
    float* orow_hi = g_wkv + ((size_t)(b * NT + thi)) * NC + h * 64;
#pragma unroll
    for (int nj = 0; nj < 4; nj++) {
        int col = wn + nj * 8 + cc * 2;
        float2 o1 = {acc[nj][0] * be_lo, acc[nj][1] * be_lo};
        float2 o2 = {acc[nj][2] * be_hi, acc[nj][3] * be_hi};
        *(float2*)&orow_lo[col] = o1;
        *(float2*)&orow_hi[col] = o2;
    }
}

// ---------------- fp16 GEMM, 128x64 block, 32x32 warp tile, 3 CTAs/SM ---------
// MODE 0: grid (64,48); sel=by>>4 picks {k,v,r}; exp for sel==0; half2 output.
// MODE 1: grid (64,16); weight slab 3 (Wo); bias bo; *gamma[t]; f32 output.
#define RS 20
#define AS (128*RS)
#define BS (64*RS)
#define STG (AS+BS)

template<int MODE>
__global__ void __launch_bounds__(256, 3) gemm_f16_n64(
    const uint32_t* __restrict__ Ah,
    float* __restrict__ Fout,
    const float* __restrict__ b0p, const float* __restrict__ b1p,
    const float* __restrict__ b2p, const float* __restrict__ gamma)
{
    extern __shared__ uint32_t sm[];
    int tid = threadIdx.x;
    int m0 = blockIdx.x * 128;
    int sel, n0;
    const float* bias;
    uint32_t* C16 = nullptr;
    if (MODE == 0) {
        sel = blockIdx.y >> 4;
        n0 = (blockIdx.y & 15) * 64;
        bias = (sel == 0) ? b0p : (sel == 1) ? b1p : b2p;
        C16 = (sel == 0) ? g_k16 : (sel == 1) ? g_v16 : g_r16;
    } else {
        sel = 3;
        n0 = blockIdx.y * 64;
        bias = b0p;
    }
    const uint32_t* Bh = g_Wh + (size_t)sel * NC * KH;

    int arow = tid >> 1, ag = (tid & 1) * 8;
    int brow = tid >> 2, bg = (tid & 3) * 4;
    const uint32_t* pAh = Ah + (size_t)(m0 + arow) * KH + ag;
    const uint32_t* pBh = Bh + (size_t)(n0 + brow) * KH + bg;
    uint32_t smem_b = (uint32_t)__cvta_generic_to_shared(sm);
    uint32_t sA = smem_b + (arow * RS + ag) * 4;
    uint32_t sB = smem_b + (AS + brow * RS + bg) * 4;

    int lane = tid & 31, warp = tid >> 5;
    int wm = (warp & 3) * 32, wn = (warp >> 2) * 32;
    int r = lane >> 2, cc = lane & 3;

    int a_base = (wm + (lane & 15)) * RS + (lane >> 4) * 4;
    int b_base = AS + (wn + ((lane >> 4) << 3) + (lane & 7)) * RS + ((lane >> 3) & 1) * 4;

    float acc[2][4][4];
#pragma unroll
    for (int a = 0; a < 2; a++)
#pragma unroll
        for (int b = 0; b < 4; b++)
#pragma unroll
            for (int q = 0; q < 4; q++) acc[a][b][q] = 0.f;

#pragma unroll
    for (int s = 0; s < 2; s++) {
        int o = s * 16;
        uint32_t dA = sA + s * STG * 4;
        uint32_t dB = sB + s * STG * 4;
        cpa16(dA, pAh + o); cpa16(dA + 16, pAh + o + 4);
        cpa16(dB, pBh + o);
        CP_COMMIT();
    }

    for (int kt = 0; kt < 32; kt++) {
        if (kt + 1 < 32) CP_WAIT1(); else CP_WAIT0();
        __syncthreads();
        if (kt + 2 < 32) {
            int slot = (kt + 2) % 3;
            int o = (kt + 2) * 16;
            uint32_t dA = sA + slot * STG * 4;
            uint32_t dB = sB + slot * STG * 4;
            cpa16(dA, pAh + o); cpa16(dA + 16, pAh + o + 4);
            cpa16(dB, pBh + o);
            CP_COMMIT();
        }

        uint32_t st = (kt % 3) * STG;
#pragma unroll
        for (int ks = 0; ks < 2; ks++) {
            uint32_t ahf[2][4];
#pragma unroll
            for (int mi = 0; mi < 2; mi++) {
                uint32_t ai = smem_b + (st + a_base + mi * 16 * RS + ks * 8) * 4;
                ldm_x4(ahf[mi], ai);
            }
#pragma unroll
            for (int jp = 0; jp < 2; jp++) {
                uint32_t bb[4];
                uint32_t bi = smem_b + (st + b_base + jp * 16 * RS + ks * 8) * 4;
                ldm_x4(bb, bi);
#pragma unroll
                for (int hf = 0; hf < 2; hf++)
#pragma unroll
                    for (int mi = 0; mi < 2; mi++)
                        mma_f16(acc[mi][jp * 2 + hf], ahf[mi], bb[hf * 2], bb[hf * 2 + 1]);
            }
        }
    }

#pragma unroll
    for (int mi = 0; mi < 2; mi++) {
        int mlo = m0 + wm + mi * 16 + r;
        int mhi = mlo + 8;
        float glo = 1.f, ghi = 1.f;
        if (MODE == 1) { glo = gamma[mlo & (NT - 1)]; ghi = gamma[mhi & (NT - 1)]; }
#pragma unroll
        for (int nj = 0; nj < 4; nj++) {
            int col = n0 + wn + nj * 8 + cc * 2;
            float b0 = bias[col], b1 = bias[col + 1];
            float v0 = acc[mi][nj][0] + b0, v1 = acc[mi][nj][1] + b1;
            float v2 = acc[mi][nj][2] + b0, v3 = acc[mi][nj][3] + b1;
            if (MODE == 0) {
                if (sel == 0) {
                    v0 = expf(fminf(fmaxf(v0, -60.f), 30.f));
                    v1 = expf(fminf(fmaxf(v1, -60.f), 30.f));
                    v2 = expf(fminf(fmaxf(v2, -60.f), 30.f));
                    v3 = expf(fminf(fmaxf(v3, -60.f), 30.f));
                }
                C16[((size_t)mlo * NC + col) >> 1] = pack2h(v0, v1);
                C16[((size_t)mhi * NC + col) >> 1] = pack2h(v2, v3);
            } else {
                v0 *= glo; v1 *= glo; v2 *= ghi; v3 *= ghi;
                float2 o01 = {v0, v1}, o23 = {v2, v3};
                *(float2*)&Fout[(size_t)mlo * NC + col] = o01;
                *(float2*)&Fout[(size_t)mhi * NC + col] = o23;
            }
        }
    }
}

// ---------------- host launch -------------------------------------------------
extern "C" void kernel_launch(void* const* d_in, const int* in_sizes, int n_in,
                              void* d_out, int out_size) {
    (void)in_sizes; (void)n_in; (void)out_size;
    const float* x      = (const float*)d_in[0];
    const float* time_w = (const float*)d_in[1];
    const float* alpha  = (const float*)d_in[2];
    const float* beta   = (const float*)d_in[3];
    const float* gamma  = (const float*)d_in[4];
    const float* Wk = (const float*)d_in[5];
    const float* bk = (const float*)d_in[6];
    const float* Wv = (const float*)d_in[7];
    const float* bv = (const float*)d_in[8];
    const float* Wr = (const float*)d_in[9];
    const float* br = (const float*)d_in[10];
    const float* Wo = (const float*)d_in[11];
    const float* bo = (const float*)d_in[12];
    float* out = (float*)d_out;

    uint32_t *Ah;
    cudaGetSymbolAddress((void**)&Ah, g_Ah);

    size_t smem = 3 * STG * 4;   // 46.08KB
    static int attr_set = 0;
    if (!attr_set) {
        cudaFuncSetAttribute(gemm_f16_n64<0>,
                             cudaFuncAttributeMaxDynamicSharedMemorySize, (int)smem);
        cudaFuncSetAttribute(gemm_f16_n64<1>,
                             cudaFuncAttributeMaxDynamicSharedMemorySize, (int)smem);
        attr_set = 1;
    }

    prep_kernel<<<PREP_B0 + PREP_B1 + PREP_B2, 256>>>(Wk, Wv, Wr, Wo, time_w, alpha, x);

    gemm_f16_n64<0><<<dim3(NM / 128, 48), 256, smem>>>(Ah, nullptr, bk, bv, br, nullptr);

    cumsumA_kernel<<<dim3(KH / 256, NB, NSEG), 256>>>();

    kvt_split_kernel<<<dim3(NT / 64, NB * NH), 256>>>();
    wkv_mma_kernel<<<dim3(NT / 64, NB * NH), 256>>>(beta);

    rwkv_split_kernel<<<NM * KH / 256, 256>>>();

    gemm_f16_n64<1><<<dim3(NM / 128, 16), 256, smem>>>(Ah, out, bo, nullptr, nullptr, gamma);
}

// round 15
// speedup vs baseline: 1.7206x; 1.0256x over previous
#include <cuda_runtime.h>
#include <cuda_fp16.h>
#include <math.h>
#include <stdint.h>

#define NB 8
#define NT 1024
#define NC 1024
#define NH 16
#define NM (NB*NT)
#define KH 512            // K/2 (fp16 pairs packed along K)
#define NSEG 8
#define TSEG (NT/NSEG)

// ---------------- scratch (static device globals, no allocation) -------------
__device__ uint32_t g_k16 [NM*KH];        // exp(clip(k)) packed half2
__device__ uint32_t g_v16 [NM*KH];        // v packed half2
__device__ uint32_t g_r16 [NM*KH];        // r packed half2
__device__ float    g_sumk[NM*NC];        // per-segment local cumsum (f32)
__device__ float    g_segtot[NB*NSEG*NC];
__device__ uint32_t g_Ah  [NM*KH];        // packed f16x2 of current A operand
__device__ uint32_t g_Wh  [4*NC*KH];      // Wk,Wv,Wr,Wo rounded to fp16 (B operand)
__device__ uint32_t g_WWh [NH*NT*KH];     // decay matrix W[h][t][u] fp16 (A of wkv)
__device__ uint32_t g_kvTh[NB*NH*64*KH];  // kv^T [bh][c][u-pairs] rounded fp16

// ---------------- helpers -----------------------------------------------------
__device__ __forceinline__ uint32_t pack2h(float a, float b) {
    __half ha = __float2half_rn(a), hb = __float2half_rn(b);
    return (uint32_t)__half_as_ushort(ha) | ((uint32_t)__half_as_ushort(hb) << 16);
}

__device__ __forceinline__ float2 unpack2h(uint32_t p) {
    __half2 h = *(__half2*)&p;
    return make_float2(__half2float(__low2half(h)), __half2float(__high2half(h)));
}

__device__ __forceinline__ void mma_f16(float* c, const uint32_t* a,
                                        uint32_t b0, uint32_t b1) {
    asm volatile(
        "mma.sync.aligned.m16n8k16.row.col.f32.f16.f16.f32 "
        "{%0,%1,%2,%3},{%4,%5,%6,%7},{%8,%9},{%0,%1,%2,%3};"
        : "+f"(c[0]), "+f"(c[1]), "+f"(c[2]), "+f"(c[3])
        : "r"(a[0]), "r"(a[1]), "r"(a[2]), "r"(a[3]), "r"(b0), "r"(b1));
}

__device__ __forceinline__ void ldm_x4(uint32_t* r, uint32_t addr) {
    asm volatile("ldmatrix.sync.aligned.m8n8.x4.shared.b16 {%0,%1,%2,%3}, [%4];"
                 : "=r"(r[0]), "=r"(r[1]), "=r"(r[2]), "=r"(r[3]) : "r"(addr));
}

__device__ __forceinline__ void cpa16(uint32_t d, const void* s) {
    asm volatile("cp.async.cg.shared.global [%0], [%1], 16;" :: "r"(d), "l"(s));
}
#define CP_COMMIT() asm volatile("cp.async.commit_group;")
#define CP_WAIT1()  asm volatile("cp.async.wait_group 1;")
#define CP_WAIT0()  asm volatile("cp.async.wait_group 0;")

// ---------------- fused prep: weights round + decay matrix + time-shift -------
#define PREP_B0 (4*NC*KH/256)
#define PREP_B1 (NH*NT*KH/256)
#define PREP_B2 (NM*KH/256)

__global__ void prep_kernel(const float* __restrict__ W0, const float* __restrict__ W1,
                            const float* __restrict__ W2, const float* __restrict__ W3,
                            const float* __restrict__ tw, const float* __restrict__ alpha,
                            const float* __restrict__ x) {
    int blk = blockIdx.x;
    if (blk < PREP_B0) {
        int i = blk * 256 + threadIdx.x;
        int w = i >> 19;
        int j = i & (NC * KH - 1);
        const float* W = (w == 0) ? W0 : (w == 1) ? W1 : (w == 2) ? W2 : W3;
        float2 v = ((const float2*)W)[j];
        g_Wh[i] = pack2h(v.x, v.y);
    } else if (blk < PREP_B0 + PREP_B1) {
        int i = (blk - PREP_B0) * 256 + threadIdx.x;
        int u = (i & (KH - 1)) * 2;
        int t = (i >> 9) & (NT - 1);
        if ((u >> 6) > (t >> 6)) return;
        int h = i >> 19;
        float w0 = 0.f, w1 = 0.f;
        if (u <= t)     w0 = tw[h * NT + 1023 - t + u]     * alpha[h * NT + u];
        if (u + 1 <= t) w1 = tw[h * NT + 1023 - t + u + 1] * alpha[h * NT + u + 1];
        g_WWh[i] = pack2h(w0, w1);
    } else {
        int i = (blk - PREP_B0 - PREP_B1) * 256 + threadIdx.x;
        int kk2 = i & (KH - 1);
        int row = i >> 9;
        int t = row & (NT - 1);
        int c = kk2 * 2;
        float a = 0.f, b = 0.f;
        if (c < NC / 2) {
            if (t != 0) {
                float2 v = *(const float2*)(x + (size_t)(row - 1) * NC + c);
                a = v.x; b = v.y;
            }
        } else {
            float2 v = *(const float2*)(x + (size_t)row * NC + c);
            a = v.x; b = v.y;
        }
        g_Ah[i] = pack2h(a, b);
    }
}

// ---------------- cumsum: per-segment local scans (half2 in, f32 out) ---------
__global__ void cumsumA_kernel() {
    int cp = blockIdx.x * 256 + threadIdx.x;      // channel pair 0..511
    int b = blockIdx.y, s = blockIdx.z;
    const uint32_t* src = g_k16 + ((size_t)(b * NT + s * TSEG)) * KH + cp;
    float* dst = g_sumk + ((size_t)(b * NT + s * TSEG)) * NC + cp * 2;
    float a0 = 0.f, a1 = 0.f;
    for (int t0 = 0; t0 < TSEG; t0 += 16) {
        uint32_t buf[16];
#pragma unroll
        for (int j = 0; j < 16; j++) buf[j] = src[(size_t)(t0 + j) * KH];
#pragma unroll
        for (int j = 0; j < 16; j++) {
            float2 kv = unpack2h(buf[j]);
            a0 += kv.x; a1 += kv.y;
            float2 o = {a0, a1};
            *(float2*)&dst[(size_t)(t0 + j) * NC] = o;
        }
    }
    float2 tot = {a0, a1};
    *(float2*)&g_segtot[(b * NSEG + s) * NC + cp * 2] = tot;
}

// ---------------- kv^T: product of fp16 k,v -> fp16 (B operand of wkv) --------
__global__ void kvt_split_kernel() {
    __shared__ float skv[64][65];
    int ut = blockIdx.x;
    int bh = blockIdx.y;
    int b = bh >> 4, h = bh & 15;
    int tid = threadIdx.x;
    int u0 = ut * 64;
    const __half* kb = (const __half*)g_k16 + ((size_t)(b * NT + u0)) * NC + h * 64;
    const __half* vb = (const __half*)g_v16 + ((size_t)(b * NT + u0)) * NC + h * 64;
#pragma unroll
    for (int rr = 0; rr < 16; rr++) {
        int i = tid + rr * 256;
        int uu = i >> 6, c = i & 63;
        skv[uu][c] = __half2float(kb[(size_t)uu * NC + c]) *
                     __half2float(vb[(size_t)uu * NC + c]);
    }
    __syncthreads();
    uint32_t* oh = g_kvTh + (size_t)bh * 64 * KH + ut * 32;
#pragma unroll
    for (int rr = 0; rr < 8; rr++) {
        int j = tid + rr * 256;
        int c = j >> 5, g = j & 31;
        oh[(size_t)c * KH + g] = pack2h(skv[g * 2][c], skv[g * 2 + 1][c]);
    }
}

// ---------------- wkv + rwkv fused (fp16 MMA, causal, 3-stage pipe) ------------
// Epilogue computes rwkv = sigmoid(r) * (wkv*beta) / sumk and writes fp16 g_Ah.
#define WR 20
#define WST (64*WR)

__global__ void __launch_bounds__(256) wkv_mma_kernel(const float* __restrict__ beta) {
    __shared__ uint32_t smw[6 * WST];       // 30KB
    int tt = blockIdx.x, bh = blockIdx.y;
    int b = bh >> 4, h = bh & 15;
    int t0 = tt * 64;
    int tid = threadIdx.x;
    int lrow = tid >> 2, lq = (tid & 3) * 4;

    const uint32_t* pWh = g_WWh + ((size_t)h * NT + t0 + lrow) * KH + lq;
    const uint32_t* pKh = g_kvTh + ((size_t)bh * 64 + lrow) * KH + lq;
    uint32_t smw_b = (uint32_t)__cvta_generic_to_shared(smw);
    uint32_t sb = smw_b + (lrow * WR + lq) * 4;

    int lane = tid & 31, warp = tid >> 5;
    int wm = (warp >> 1) * 16, wn = (warp & 1) * 32;
    int r = lane >> 2, cc = lane & 3;

    int a_base = (wm + (lane & 15)) * WR + (lane >> 4) * 4;
    int b_base = (wn + ((lane >> 4) << 3) + (lane & 7)) * WR + ((lane >> 3) & 1) * 4;

    float acc[4][4];
#pragma unroll
    for (int i = 0; i < 4; i++)
#pragma unroll
        for (int j = 0; j < 4; j++) acc[i][j] = 0.f;

    int nut = 2 * (tt + 1);

#pragma unroll
    for (int s = 0; s < 2; s++) {
        uint32_t d = sb + s * WST * 4;
        int o = s * 16;
        cpa16(d,               pWh + o);
        cpa16(d + 3 * WST * 4, pKh + o);
        CP_COMMIT();
    }

    for (int ut = 0; ut < nut; ut++) {
        if (ut + 1 < nut) CP_WAIT1(); else CP_WAIT0();
        __syncthreads();
        if (ut + 2 < nut) {
            int slot = (ut + 2) % 3;
            uint32_t d = sb + slot * WST * 4;
            int o = (ut + 2) * 16;
            cpa16(d,               pWh + o);
            cpa16(d + 3 * WST * 4, pKh + o);
            CP_COMMIT();
        }

        uint32_t stoff = (ut % 3) * WST;
#pragma unroll
        for (int ks = 0; ks < 2; ks++) {
            uint32_t ah[4];
            uint32_t ai = smw_b + (stoff + a_base + ks * 8) * 4;
            ldm_x4(ah, ai);

            uint32_t bhf[2][4];
#pragma unroll
            for (int jp = 0; jp < 2; jp++) {
                uint32_t bi = smw_b + (stoff + b_base + jp * 16 * WR + ks * 8) * 4;
                ldm_x4(bhf[jp], bi + 3 * WST * 4);
            }
#pragma unroll
            for (int jp = 0; jp < 2; jp++)
#pragma unroll
                for (int hf = 0; hf < 2; hf++)
                    mma_f16(acc[jp * 2 + hf], ah, bhf[jp][hf * 2], bhf[jp][hf * 2 + 1]);
        }
    }

    // ---- fused rwkv epilogue ----
#pragma unroll
    for (int ri = 0; ri < 2; ri++) {
        int t = t0 + wm + r + ri * 8;
        float be = beta[h * NT + t];
        size_t grow = (size_t)(b * NT + t);
        int nseg = t >> 7;
#pragma unroll
        for (int nj = 0; nj < 4; nj++) {
            int col = h * 64 + wn + nj * 8 + cc * 2;
            // segment offset (g_segtot is small, L2 resident)
            float so0 = 0.f, so1 = 0.f;
            for (int sg = 0; sg < nseg; sg++) {
                float2 st = *(const float2*)&g_segtot[(b * NSEG + sg) * NC + col];
                so0 += st.x; so1 += st.y;
            }
            float2 sk = *(const float2*)&g_sumk[grow * NC + col];
            float2 rv = unpack2h(g_r16[(grow * NC + col) >> 1]);
            float w0 = acc[nj][ri * 2 + 0] * be;
            float w1 = acc[nj][ri * 2 + 1] * be;
            float o0 = (1.f / (1.f + expf(-rv.x))) * w0 / (sk.x + so0);
            float o1 = (1.f / (1.f + expf(-rv.y))) * w1 / (sk.y + so1);
            g_Ah[(grow * NC + col) >> 1] = pack2h(o0, o1);
        }
    }
}

// ---------------- fp16 GEMM, 128x64 block, 32x32 warp tile, 3 CTAs/SM ---------
// MODE 0: grid (64,48); sel=by>>4 picks {k,v,r}; exp for sel==0; half2 output.
// MODE 1: grid (64,16); weight slab 3 (Wo); bias bo; *gamma[t]; f32 output.
#define RS 20
#define AS (128*RS)
#define BS (64*RS)
#define STG (AS+BS)

template<int MODE>
__global__ void __launch_bounds__(256, 3) gemm_f16_n64(
    const uint32_t* __restrict__ Ah,
    float* __restrict__ Fout,
    const float* __restrict__ b0p, const float* __restrict__ b1p,
    const float* __restrict__ b2p, const float* __restrict__ gamma)
{
    extern __shared__ uint32_t sm[];
    int tid = threadIdx.x;
    int m0 = blockIdx.x * 128;
    int sel, n0;
    const float* bias;
    uint32_t* C16 = nullptr;
    if (MODE == 0) {
        sel = blockIdx.y >> 4;
        n0 = (blockIdx.y & 15) * 64;
        bias = (sel == 0) ? b0p : (sel == 1) ? b1p : b2p;
        C16 = (sel == 0) ? g_k16 : (sel == 1) ? g_v16 : g_r16;
    } else {
        sel = 3;
        n0 = blockIdx.y * 64;
        bias = b0p;
    }
    const uint32_t* Bh = g_Wh + (size_t)sel * NC * KH;

    int arow = tid >> 1, ag = (tid & 1) * 8;
    int brow = tid >> 2, bg = (tid & 3) * 4;
    const uint32_t* pAh = Ah + (size_t)(m0 + arow) * KH + ag;
    const uint32_t* pBh = Bh + (size_t)(n0 + brow) * KH + bg;
    uint32_t smem_b = (uint32_t)__cvta_generic_to_shared(sm);
    uint32_t sA = smem_b + (arow * RS + ag) * 4;
    uint32_t sB = smem_b + (AS + brow * RS + bg) * 4;

    int lane = tid & 31, warp = tid >> 5;
    int wm = (warp & 3) * 32, wn = (warp >> 2) * 32;
    int r = lane >> 2, cc = lane & 3;

    int a_base = (wm + (lane & 15)) * RS + (lane >> 4) * 4;
    int b_base = AS + (wn + ((lane >> 4) << 3) + (lane & 7)) * RS + ((lane >> 3) & 1) * 4;

    float acc[2][4][4];
#pragma unroll
    for (int a = 0; a < 2; a++)
#pragma unroll
        for (int b = 0; b < 4; b++)
#pragma unroll
            for (int q = 0; q < 4; q++) acc[a][b][q] = 0.f;

#pragma unroll
    for (int s = 0; s < 2; s++) {
        int o = s * 16;
        uint32_t dA = sA + s * STG * 4;
        uint32_t dB = sB + s * STG * 4;
        cpa16(dA, pAh + o); cpa16(dA + 16, pAh + o + 4);
        cpa16(dB, pBh + o);
        CP_COMMIT();
    }

    for (int kt = 0; kt < 32; kt++) {
        if (kt + 1 < 32) CP_WAIT1(); else CP_WAIT0();
        __syncthreads();
        if (kt + 2 < 32) {
            int slot = (kt + 2) % 3;
            int o = (kt + 2) * 16;
            uint32_t dA = sA + slot * STG * 4;
            uint32_t dB = sB + slot * STG * 4;
            cpa16(dA, pAh + o); cpa16(dA + 16, pAh + o + 4);
            cpa16(dB, pBh + o);
            CP_COMMIT();
        }

        uint32_t st = (kt % 3) * STG;
#pragma unroll
        for (int ks = 0; ks < 2; ks++) {
            uint32_t ahf[2][4];
#pragma unroll
            for (int mi = 0; mi < 2; mi++) {
                uint32_t ai = smem_b + (st + a_base + mi * 16 * RS + ks * 8) * 4;
                ldm_x4(ahf[mi], ai);
            }
#pragma unroll
            for (int jp = 0; jp < 2; jp++) {
                uint32_t bb[4];
                uint32_t bi = smem_b + (st + b_base + jp * 16 * RS + ks * 8) * 4;
                ldm_x4(bb, bi);
#pragma unroll
                for (int hf = 0; hf < 2; hf++)
#pragma unroll
                    for (int mi = 0; mi < 2; mi++)
                        mma_f16(acc[mi][jp * 2 + hf], ahf[mi], bb[hf * 2], bb[hf * 2 + 1]);
            }
        }
    }

#pragma unroll
    for (int mi = 0; mi < 2; mi++) {
        int mlo = m0 + wm + mi * 16 + r;
        int mhi = mlo + 8;
        float glo = 1.f, ghi = 1.f;
        if (MODE == 1) { glo = gamma[mlo & (NT - 1)]; ghi = gamma[mhi & (NT - 1)]; }
#pragma unroll
        for (int nj = 0; nj < 4; nj++) {
            int col = n0 + wn + nj * 8 + cc * 2;
            float b0 = bias[col], b1 = bias[col + 1];
            float v0 = acc[mi][nj][0] + b0, v1 = acc[mi][nj][1] + b1;
            float v2 = acc[mi][nj][2] + b0, v3 = acc[mi][nj][3] + b1;
            if (MODE == 0) {
                if (sel == 0) {
                    v0 = expf(fminf(fmaxf(v0, -60.f), 30.f));
                    v1 = expf(fminf(fmaxf(v1, -60.f), 30.f));
                    v2 = expf(fminf(fmaxf(v2, -60.f), 30.f));
                    v3 = expf(fminf(fmaxf(v3, -60.f), 30.f));
                }
                C16[((size_t)mlo * NC + col) >> 1] = pack2h(v0, v1);
                C16[((size_t)mhi * NC + col) >> 1] = pack2h(v2, v3);
            } else {
                v0 *= glo; v1 *= glo; v2 *= ghi; v3 *= ghi;
                float2 o01 = {v0, v1}, o23 = {v2, v3};
                *(float2*)&Fout[(size_t)mlo * NC + col] = o01;
                *(float2*)&Fout[(size_t)mhi * NC + col] = o23;
            }
        }
    }
}

// ---------------- host launch -------------------------------------------------
extern "C" void kernel_launch(void* const* d_in, const int* in_sizes, int n_in,
                              void* d_out, int out_size) {
    (void)in_sizes; (void)n_in; (void)out_size;
    const float* x      = (const float*)d_in[0];
    const float* time_w = (const float*)d_in[1];
    const float* alpha  = (const float*)d_in[2];
    const float* beta   = (const float*)d_in[3];
    const float* gamma  = (const float*)d_in[4];
    const float* Wk = (const float*)d_in[5];
    const float* bk = (const float*)d_in[6];
    const float* Wv = (const float*)d_in[7];
    const float* bv = (const float*)d_in[8];
    const float* Wr = (const float*)d_in[9];
    const float* br = (const float*)d_in[10];
    const float* Wo = (const float*)d_in[11];
    const float* bo = (const float*)d_in[12];
    float* out = (float*)d_out;

    uint32_t *Ah;
    cudaGetSymbolAddress((void**)&Ah, g_Ah);

    size_t smem = 3 * STG * 4;   // 46.08KB
    static int attr_set = 0;
    if (!attr_set) {
        cudaFuncSetAttribute(gemm_f16_n64<0>,
                             cudaFuncAttributeMaxDynamicSharedMemorySize, (int)smem);
        cudaFuncSetAttribute(gemm_f16_n64<1>,
                             cudaFuncAttributeMaxDynamicSharedMemorySize, (int)smem);
        attr_set = 1;
    }

    prep_kernel<<<PREP_B0 + PREP_B1 + PREP_B2, 256>>>(Wk, Wv, Wr, Wo, time_w, alpha, x);

    gemm_f16_n64<0><<<dim3(NM / 128, 48), 256, smem>>>(Ah, nullptr, bk, bv, br, nullptr);

    cumsumA_kernel<<<dim3(KH / 256, NB, NSEG), 256>>>();

    kvt_split_kernel<<<dim3(NT / 64, NB * NH), 256>>>();

    wkv_mma_kernel<<<dim3(NT / 64, NB * NH), 256>>>(beta);

    gemm_f16_n64<1><<<dim3(NM / 128, 16), 256, smem>>>(Ah, out, bo, nullptr, nullptr, gamma);
}

// round 16
// speedup vs baseline: 1.7714x; 1.0295x over previous
#include <cuda_runtime.h>
#include <cuda_fp16.h>
#include <math.h>
#include <stdint.h>

#define NB 8
#define NT 1024
#define NC 1024
#define NH 16
#define NM (NB*NT)
#define KH 512            // K/2 (fp16 pairs packed along K)
#define NSEG 8
#define TSEG (NT/NSEG)

// ---------------- scratch (static device globals, no allocation) -------------
__device__ uint32_t g_k16 [NM*KH];        // exp(clip(k)) packed half2
__device__ uint32_t g_v16 [NM*KH];        // v packed half2
__device__ uint32_t g_r16 [NM*KH];        // r packed half2
__device__ float    g_sumk[NM*NC];        // per-segment local cumsum (f32)
__device__ float    g_segtot[NB*NSEG*NC];
__device__ uint32_t g_Ah  [NM*KH];        // packed f16x2 of current A operand
__device__ uint32_t g_Wh  [4*NC*KH];      // Wk,Wv,Wr,Wo rounded to fp16 (B operand)
__device__ uint32_t g_WWh [NH*NT*KH];     // decay matrix W[h][t][u] fp16 (A of wkv)
__device__ uint32_t g_kvTh[NB*NH*64*KH];  // kv^T [bh][c][u-pairs] rounded fp16

// ---------------- helpers -----------------------------------------------------
__device__ __forceinline__ uint32_t pack2h(float a, float b) {
    __half ha = __float2half_rn(a), hb = __float2half_rn(b);
    return (uint32_t)__half_as_ushort(ha) | ((uint32_t)__half_as_ushort(hb) << 16);
}

__device__ __forceinline__ float2 unpack2h(uint32_t p) {
    __half2 h = *(__half2*)&p;
    return make_float2(__half2float(__low2half(h)), __half2float(__high2half(h)));
}

__device__ __forceinline__ void mma_f16(float* c, const uint32_t* a,
                                        uint32_t b0, uint32_t b1) {
    asm volatile(
        "mma.sync.aligned.m16n8k16.row.col.f32.f16.f16.f32 "
        "{%0,%1,%2,%3},{%4,%5,%6,%7},{%8,%9},{%0,%1,%2,%3};"
        : "+f"(c[0]), "+f"(c[1]), "+f"(c[2]), "+f"(c[3])
        : "r"(a[0]), "r"(a[1]), "r"(a[2]), "r"(a[3]), "r"(b0), "r"(b1));
}

__device__ __forceinline__ void ldm_x4(uint32_t* r, uint32_t addr) {
    asm volatile("ldmatrix.sync.aligned.m8n8.x4.shared.b16 {%0,%1,%2,%3}, [%4];"
                 : "=r"(r[0]), "=r"(r[1]), "=r"(r[2]), "=r"(r[3]) : "r"(addr));
}

__device__ __forceinline__ void cpa16(uint32_t d, const void* s) {
    asm volatile("cp.async.cg.shared.global [%0], [%1], 16;" :: "r"(d), "l"(s));
}
#define CP_COMMIT() asm volatile("cp.async.commit_group;")
#define CP_WAIT1()  asm volatile("cp.async.wait_group 1;")
#define CP_WAIT0()  asm volatile("cp.async.wait_group 0;")

// ---------------- fused prep: weights round + decay matrix + time-shift -------
#define PREP_B0 (4*NC*KH/256)
#define PREP_B1 (NH*NT*KH/256)
#define PREP_B2 (NM*KH/256)

__global__ void prep_kernel(const float* __restrict__ W0, const float* __restrict__ W1,
                            const float* __restrict__ W2, const float* __restrict__ W3,
                            const float* __restrict__ tw, const float* __restrict__ alpha,
                            const float* __restrict__ x) {
    int blk = blockIdx.x;
    if (blk < PREP_B0) {
        int i = blk * 256 + threadIdx.x;
        int w = i >> 19;
        int j = i & (NC * KH - 1);
        const float* W = (w == 0) ? W0 : (w == 1) ? W1 : (w == 2) ? W2 : W3;
        float2 v = ((const float2*)W)[j];
        g_Wh[i] = pack2h(v.x, v.y);
    } else if (blk < PREP_B0 + PREP_B1) {
        int i = (blk - PREP_B0) * 256 + threadIdx.x;
        int u = (i & (KH - 1)) * 2;
        int t = (i >> 9) & (NT - 1);
        if ((u >> 6) > (t >> 6)) return;
        int h = i >> 19;
        float w0 = 0.f, w1 = 0.f;
        if (u <= t)     w0 = tw[h * NT + 1023 - t + u]     * alpha[h * NT + u];
        if (u + 1 <= t) w1 = tw[h * NT + 1023 - t + u + 1] * alpha[h * NT + u + 1];
        g_WWh[i] = pack2h(w0, w1);
    } else {
        int i = (blk - PREP_B0 - PREP_B1) * 256 + threadIdx.x;
        int kk2 = i & (KH - 1);
        int row = i >> 9;
        int t = row & (NT - 1);
        int c = kk2 * 2;
        float a = 0.f, b = 0.f;
        if (c < NC / 2) {
            if (t != 0) {
                float2 v = *(const float2*)(x + (size_t)(row - 1) * NC + c);
                a = v.x; b = v.y;
            }
        } else {
            float2 v = *(const float2*)(x + (size_t)row * NC + c);
            a = v.x; b = v.y;
        }
        g_Ah[i] = pack2h(a, b);
    }
}

// ---------------- fused: cumsum (segment scans) + kv^T build ------------------
// Blocks [0, 128): cumsum over (cp_blk, b, s). Blocks [128, 128+2048): kvt tiles.
#define CS_BLKS 128

__global__ void cumsum_kvt_kernel() {
    int blk = blockIdx.x;
    if (blk < CS_BLKS) {
        int cp = (blk & 1) * 256 + threadIdx.x;   // channel pair 0..511
        int b = (blk >> 1) & 7;
        int s = blk >> 4;
        const uint32_t* src = g_k16 + ((size_t)(b * NT + s * TSEG)) * KH + cp;
        float* dst = g_sumk + ((size_t)(b * NT + s * TSEG)) * NC + cp * 2;
        float a0 = 0.f, a1 = 0.f;
        for (int t0 = 0; t0 < TSEG; t0 += 16) {
            uint32_t buf[16];
#pragma unroll
            for (int j = 0; j < 16; j++) buf[j] = src[(size_t)(t0 + j) * KH];
#pragma unroll
            for (int j = 0; j < 16; j++) {
                float2 kv = unpack2h(buf[j]);
                a0 += kv.x; a1 += kv.y;
                float2 o = {a0, a1};
                *(float2*)&dst[(size_t)(t0 + j) * NC] = o;
            }
        }
        float2 tot = {a0, a1};
        *(float2*)&g_segtot[(b * NSEG + s) * NC + cp * 2] = tot;
    } else {
        __shared__ float skv[64][65];
        int id = blk - CS_BLKS;
        int ut = id & 15;
        int bh = id >> 4;
        int b = bh >> 4, h = bh & 15;
        int tid = threadIdx.x;
        int u0 = ut * 64;
        const __half* kb = (const __half*)g_k16 + ((size_t)(b * NT + u0)) * NC + h * 64;
        const __half* vb = (const __half*)g_v16 + ((size_t)(b * NT + u0)) * NC + h * 64;
#pragma unroll
        for (int rr = 0; rr < 16; rr++) {
            int i = tid + rr * 256;
            int uu = i >> 6, c = i & 63;
            skv[uu][c] = __half2float(kb[(size_t)uu * NC + c]) *
                         __half2float(vb[(size_t)uu * NC + c]);
        }
        __syncthreads();
        uint32_t* oh = g_kvTh + (size_t)bh * 64 * KH + ut * 32;
#pragma unroll
        for (int rr = 0; rr < 8; rr++) {
            int j = tid + rr * 256;
            int c = j >> 5, g = j & 31;
            oh[(size_t)c * KH + g] = pack2h(skv[g * 2][c], skv[g * 2 + 1][c]);
        }
    }
}

// ---------------- wkv + rwkv fused (fp16 MMA, causal, 3-stage pipe) ------------
#define WR 20
#define WST (64*WR)

__global__ void __launch_bounds__(256) wkv_mma_kernel(const float* __restrict__ beta) {
    __shared__ uint32_t smw[6 * WST];       // 30KB
    int tt = blockIdx.x, bh = blockIdx.y;
    int b = bh >> 4, h = bh & 15;
    int t0 = tt * 64;
    int tid = threadIdx.x;
    int lrow = tid >> 2, lq = (tid & 3) * 4;

    const uint32_t* pWh = g_WWh + ((size_t)h * NT + t0 + lrow) * KH + lq;
    const uint32_t* pKh = g_kvTh + ((size_t)bh * 64 + lrow) * KH + lq;
    uint32_t smw_b = (uint32_t)__cvta_generic_to_shared(smw);
    uint32_t sb = smw_b + (lrow * WR + lq) * 4;

    int lane = tid & 31, warp = tid >> 5;
    int wm = (warp >> 1) * 16, wn = (warp & 1) * 32;
    int r = lane >> 2, cc = lane & 3;

    int a_base = (wm + (lane & 15)) * WR + (lane >> 4) * 4;
    int b_base = (wn + ((lane >> 4) << 3) + (lane & 7)) * WR + ((lane >> 3) & 1) * 4;

    float acc[4][4];
#pragma unroll
    for (int i = 0; i < 4; i++)
#pragma unroll
        for (int j = 0; j < 4; j++) acc[i][j] = 0.f;

    int nut = 2 * (tt + 1);

#pragma unroll
    for (int s = 0; s < 2; s++) {
        uint32_t d = sb + s * WST * 4;
        int o = s * 16;
        cpa16(d,               pWh + o);
        cpa16(d + 3 * WST * 4, pKh + o);
        CP_COMMIT();
    }

    for (int ut = 0; ut < nut; ut++) {
        if (ut + 1 < nut) CP_WAIT1(); else CP_WAIT0();
        __syncthreads();
        if (ut + 2 < nut) {
            int slot = (ut + 2) % 3;
            uint32_t d = sb + slot * WST * 4;
            int o = (ut + 2) * 16;
            cpa16(d,               pWh + o);
            cpa16(d + 3 * WST * 4, pKh + o);
            CP_COMMIT();
        }

        uint32_t stoff = (ut % 3) * WST;
#pragma unroll
        for (int ks = 0; ks < 2; ks++) {
            uint32_t ah[4];
            uint32_t ai = smw_b + (stoff + a_base + ks * 8) * 4;
            ldm_x4(ah, ai);

            uint32_t bhf[2][4];
#pragma unroll
            for (int jp = 0; jp < 2; jp++) {
                uint32_t bi = smw_b + (stoff + b_base + jp * 16 * WR + ks * 8) * 4;
                ldm_x4(bhf[jp], bi + 3 * WST * 4);
            }
#pragma unroll
            for (int jp = 0; jp < 2; jp++)
#pragma unroll
                for (int hf = 0; hf < 2; hf++)
                    mma_f16(acc[jp * 2 + hf], ah, bhf[jp][hf * 2], bhf[jp][hf * 2 + 1]);
        }
    }

    // ---- fused rwkv epilogue (segment offsets hoisted: nseg constant per tile,
    //      and identical for both ri rows) ----
    int nseg = t0 >> 7;
    float so0[4], so1[4];
#pragma unroll
    for (int nj = 0; nj < 4; nj++) {
        int col = h * 64 + wn + nj * 8 + cc * 2;
        float s0 = 0.f, s1 = 0.f;
        for (int sg = 0; sg < nseg; sg++) {
            float2 st = *(const float2*)&g_segtot[(b * NSEG + sg) * NC + col];
            s0 += st.x; s1 += st.y;
        }
        so0[nj] = s0; so1[nj] = s1;
    }
#pragma unroll
    for (int ri = 0; ri < 2; ri++) {
        int t = t0 + wm + r + ri * 8;
        float be = beta[h * NT + t];
        size_t grow = (size_t)(b * NT + t);
#pragma unroll
        for (int nj = 0; nj < 4; nj++) {
            int col = h * 64 + wn + nj * 8 + cc * 2;
            float2 sk = *(const float2*)&g_sumk[grow * NC + col];
            float2 rv = unpack2h(g_r16[(grow * NC + col) >> 1]);
            float w0 = acc[nj][ri * 2 + 0] * be;
            float w1 = acc[nj][ri * 2 + 1] * be;
            float o0 = (1.f / (1.f + expf(-rv.x))) * w0 / (sk.x + so0[nj]);
            float o1 = (1.f / (1.f + expf(-rv.y))) * w1 / (sk.y + so1[nj]);
            g_Ah[(grow * NC + col) >> 1] = pack2h(o0, o1);
        }
    }
}

// ---------------- fp16 GEMM, 128x64 block, 32x32 warp tile, 3 CTAs/SM ---------
// MODE 0: grid (64,48); sel=by>>4 picks {k,v,r}; exp for sel==0; half2 output.
// MODE 1: grid (64,16); weight slab 3 (Wo); bias bo; *gamma[t]; f32 output.
#define RS 20
#define AS (128*RS)
#define BS (64*RS)
#define STG (AS+BS)

template<int MODE>
__global__ void __launch_bounds__(256, 3) gemm_f16_n64(
    const uint32_t* __restrict__ Ah,
    float* __restrict__ Fout,
    const float* __restrict__ b0p, const float* __restrict__ b1p,
    const float* __restrict__ b2p, const float* __restrict__ gamma)
{
    extern __shared__ uint32_t sm[];
    int tid = threadIdx.x;
    int m0 = blockIdx.x * 128;
    int sel, n0;
    const float* bias;
    uint32_t* C16 = nullptr;
    if (MODE == 0) {
        sel = blockIdx.y >> 4;
        n0 = (blockIdx.y & 15) * 64;
        bias = (sel == 0) ? b0p : (sel == 1) ? b1p : b2p;
        C16 = (sel == 0) ? g_k16 : (sel == 1) ? g_v16 : g_r16;
    } else {
        sel = 3;
        n0 = blockIdx.y * 64;
        bias = b0p;
    }
    const uint32_t* Bh = g_Wh + (size_t)sel * NC * KH;

    int arow = tid >> 1, ag = (tid & 1) * 8;
    int brow = tid >> 2, bg = (tid & 3) * 4;
    const uint32_t* pAh = Ah + (size_t)(m0 + arow) * KH + ag;
    const uint32_t* pBh = Bh + (size_t)(n0 + brow) * KH + bg;
    uint32_t smem_b = (uint32_t)__cvta_generic_to_shared(sm);
    uint32_t sA = smem_b + (arow * RS + ag) * 4;
    uint32_t sB = smem_b + (AS + brow * RS + bg) * 4;

    int lane = tid & 31, warp = tid >> 5;
    int wm = (warp & 3) * 32, wn = (warp >> 2) * 32;
    int r = lane >> 2, cc = lane & 3;

    int a_base = (wm + (lane & 15)) * RS + (lane >> 4) * 4;
    int b_base = AS + (wn + ((lane >> 4) << 3) + (lane & 7)) * RS + ((lane >> 3) & 1) * 4;

    float acc[2][4][4];
#pragma unroll
    for (int a = 0; a < 2; a++)
#pragma unroll
        for (int b = 0; b < 4; b++)
#pragma unroll
            for (int q = 0; q < 4; q++) acc[a][b][q] = 0.f;

#pragma unroll
    for (int s = 0; s < 2; s++) {
        int o = s * 16;
        uint32_t dA = sA + s * STG * 4;
        uint32_t dB = sB + s * STG * 4;
        cpa16(dA, pAh + o); cpa16(dA + 16, pAh + o + 4);
        cpa16(dB, pBh + o);
        CP_COMMIT();
    }

    for (int kt = 0; kt < 32; kt++) {
        if (kt + 1 < 32) CP_WAIT1(); else CP_WAIT0();
        __syncthreads();
        if (kt + 2 < 32) {
            int slot = (kt + 2) % 3;
            int o = (kt + 2) * 16;
            uint32_t dA = sA + slot * STG * 4;
            uint32_t dB = sB + slot * STG * 4;
            cpa16(dA, pAh + o); cpa16(dA + 16, pAh + o + 4);
            cpa16(dB, pBh + o);
            CP_COMMIT();
        }

        uint32_t st = (kt % 3) * STG;
#pragma unroll
        for (int ks = 0; ks < 2; ks++) {
            uint32_t ahf[2][4];
#pragma unroll
            for (int mi = 0; mi < 2; mi++) {
                uint32_t ai = smem_b + (st + a_base + mi * 16 * RS + ks * 8) * 4;
                ldm_x4(ahf[mi], ai);
            }
#pragma unroll
            for (int jp = 0; jp < 2; jp++) {
                uint32_t bb[4];
                uint32_t bi = smem_b + (st + b_base + jp * 16 * RS + ks * 8) * 4;
                ldm_x4(bb, bi);
#pragma unroll
                for (int hf = 0; hf < 2; hf++)
#pragma unroll
                    for (int mi = 0; mi < 2; mi++)
                        mma_f16(acc[mi][jp * 2 + hf], ahf[mi], bb[hf * 2], bb[hf * 2 + 1]);
            }
        }
    }

#pragma unroll
    for (int mi = 0; mi < 2; mi++) {
        int mlo = m0 + wm + mi * 16 + r;
        int mhi = mlo + 8;
        float glo = 1.f, ghi = 1.f;
        if (MODE == 1) { glo = gamma[mlo & (NT - 1)]; ghi = gamma[mhi & (NT - 1)]; }
#pragma unroll
        for (int nj = 0; nj < 4; nj++) {
            int col = n0 + wn + nj * 8 + cc * 2;
            float b0 = bias[col], b1 = bias[col + 1];
            float v0 = acc[mi][nj][0] + b0, v1 = acc[mi][nj][1] + b1;
            float v2 = acc[mi][nj][2] + b0, v3 = acc[mi][nj][3] + b1;
            if (MODE == 0) {
                if (sel == 0) {
                    v0 = expf(fminf(fmaxf(v0, -60.f), 30.f));
                    v1 = expf(fminf(fmaxf(v1, -60.f), 30.f));
                    v2 = expf(fminf(fmaxf(v2, -60.f), 30.f));
                    v3 = expf(fminf(fmaxf(v3, -60.f), 30.f));
                }
                C16[((size_t)mlo * NC + col) >> 1] = pack2h(v0, v1);
                C16[((size_t)mhi * NC + col) >> 1] = pack2h(v2, v3);
            } else {
                v0 *= glo; v1 *= glo; v2 *= ghi; v3 *= ghi;
                float2 o01 = {v0, v1}, o23 = {v2, v3};
                *(float2*)&Fout[(size_t)mlo * NC + col] = o01;
                *(float2*)&Fout[(size_t)mhi * NC + col] = o23;
            }
        }
    }
}

// ---------------- host launch -------------------------------------------------
extern "C" void kernel_launch(void* const* d_in, const int* in_sizes, int n_in,
                              void* d_out, int out_size) {
    (void)in_sizes; (void)n_in; (void)out_size;
    const float* x      = (const float*)d_in[0];
    const float* time_w = (const float*)d_in[1];
    const float* alpha  = (const float*)d_in[2];
    const float* beta   = (const float*)d_in[3];
    const float* gamma  = (const float*)d_in[4];
    const float* Wk = (const float*)d_in[5];
    const float* bk = (const float*)d_in[6];
    const float* Wv = (const float*)d_in[7];
    const float* bv = (const float*)d_in[8];
    const float* Wr = (const float*)d_in[9];
    const float* br = (const float*)d_in[10];
    const float* Wo = (const float*)d_in[11];
    const float* bo = (const float*)d_in[12];
    float* out = (float*)d_out;

    uint32_t *Ah;
    cudaGetSymbolAddress((void**)&Ah, g_Ah);

    size_t smem = 3 * STG * 4;   // 46.08KB
    static int attr_set = 0;
    if (!attr_set) {
        cudaFuncSetAttribute(gemm_f16_n64<0>,
                             cudaFuncAttributeMaxDynamicSharedMemorySize, (int)smem);
        cudaFuncSetAttribute(gemm_f16_n64<1>,
                             cudaFuncAttributeMaxDynamicSharedMemorySize, (int)smem);
        attr_set = 1;
    }

    prep_kernel<<<PREP_B0 + PREP_B1 + PREP_B2, 256>>>(Wk, Wv, Wr, Wo, time_w, alpha, x);

    gemm_f16_n64<0><<<dim3(NM / 128, 48), 256, smem>>>(Ah, nullptr, bk, bv, br, nullptr);

    cumsum_kvt_kernel<<<CS_BLKS + NB * NH * (NT / 64), 256>>>();

    wkv_mma_kernel<<<dim3(NT / 64, NB * NH), 256>>>(beta);

    gemm_f16_n64<1><<<dim3(NM / 128, 16), 256, smem>>>(Ah, out, bo, nullptr, nullptr, gamma);
}